// round 2
// baseline (speedup 1.0000x reference)
#include <cuda_runtime.h>
#include <cuda_bf16.h>

// ---------------- problem constants ----------------
#define S_LEN    661500
#define HOP      512
#define T_FRAMES 1292
#define N_BINS   1025
#define N_MELS   128
#define BW       96            // padded mel band width (max real width ~56)

// ---------------- device statics (no allocation allowed) ----------------
__device__ float  g_win[2048];        // periodic hann
__device__ float2 g_tw1024[768];      // W_1024^k = exp(-2*pi*i*k/1024), k<768
__device__ float2 g_tw2048[1025];     // W_2048^k, k<=1024 (real-unpack)
__device__ float  g_band[N_MELS * BW];// band-compacted filterbank, zero padded
__device__ int    g_lo[N_MELS];       // band start bin per mel row

// ---------------- init: window + twiddles ----------------
__global__ void init_misc() {
    int i = blockIdx.x * blockDim.x + threadIdx.x;
    if (i < 2048) g_win[i] = 0.5f - 0.5f * cospif((float)i / 1024.0f);
    if (i < 768) {
        float s, c; sincospif(-(float)i / 512.0f, &s, &c);
        g_tw1024[i] = make_float2(c, s);
    }
    if (i < 1025) {
        float s, c; sincospif(-(float)i / 1024.0f, &s, &c);
        g_tw2048[i] = make_float2(c, s);
    }
}

// ---------------- init: extract nonzero band per mel row ----------------
__global__ void init_band(const float* __restrict__ fb) {
    __shared__ int slo, shi;
    const int m = blockIdx.x;
    const int tid = threadIdx.x;
    if (tid == 0) { slo = N_BINS; shi = -1; }
    __syncthreads();
    int l = N_BINS, h = -1;
    for (int k = tid; k < N_BINS; k += blockDim.x) {
        if (fb[m * N_BINS + k] != 0.0f) { l = min(l, k); h = max(h, k); }
    }
    atomicMin(&slo, l);
    atomicMax(&shi, h);
    __syncthreads();
    const int lo = (shi >= 0) ? slo : 0;
    for (int i = tid; i < BW; i += blockDim.x) {
        int k = lo + i;
        g_band[m * BW + i] = (k <= shi && k < N_BINS) ? fb[m * N_BINS + k] : 0.0f;
    }
    if (tid == 0) g_lo[m] = lo;
}

// ---------------- fused: reflect-pad + window + rFFT (radix-4) + power + mel ----------------
// One block per (frame t, batch b); handles BOTH channels (packed-real 1024-pt FFT each).
__global__ __launch_bounds__(512) void fft_mel_kernel(const float* __restrict__ x,
                                                      float* __restrict__ out) {
    __shared__ float  zr0[1024], zi0[1024], zr1[1024], zi1[1024];
    __shared__ float2 tws[768];
    __shared__ float  pw[2][N_BINS + BW];   // power spectra, zero-padded tail

    const int tid = threadIdx.x;
    const int t   = blockIdx.x;
    const int b   = blockIdx.y;
    const float2* xp = (const float2*)x + (size_t)b * S_LEN;  // (ch0, ch1) per sample

    // stage twiddles into smem
    for (int i = tid; i < 768; i += 512) tws[i] = g_tw1024[i];
    // zero the power-padding tail (read-overrun region of the mel loop)
    if (tid < BW) { pw[0][N_BINS + tid] = 0.0f; pw[1][N_BINS + tid] = 0.0f; }

    // load reflect-padded, windowed frame; pack real pairs -> complex;
    // write base-4 digit-reversed so 5 radix-4 DIT stages yield natural order.
    const int base = t * HOP - 1024;
    for (int k = tid; k < 1024; k += 512) {
        int p0 = base + 2 * k;
        int p1 = p0 + 1;
        p0 = (p0 < 0) ? -p0 : ((p0 >= S_LEN) ? 2 * S_LEN - 2 - p0 : p0);
        p1 = (p1 < 0) ? -p1 : ((p1 >= S_LEN) ? 2 * S_LEN - 2 - p1 : p1);
        float2 v0 = xp[p0];
        float2 v1 = xp[p1];
        float  w0 = g_win[2 * k], w1 = g_win[2 * k + 1];
        unsigned r = __brev((unsigned)k) >> 22;          // 10-bit bit-reverse
        r = ((r & 0x155u) << 1) | ((r >> 1) & 0x155u);   // swap bit pairs -> base-4 digit-reverse
        zr0[r] = w0 * v0.x; zi0[r] = w1 * v1.x;          // channel 0
        zr1[r] = w0 * v0.y; zi1[r] = w1 * v1.y;          // channel 1
    }
    __syncthreads();

    // 5 radix-4 DIT stages; warps 0-7 -> ch0, warps 8-15 -> ch1 (1 butterfly/thread/stage)
    float* zr = (tid < 256) ? zr0 : zr1;
    float* zi = (tid < 256) ? zi0 : zi1;
    const int bf = tid & 255;
#pragma unroll
    for (int len = 4; len <= 1024; len <<= 2) {
        const int q     = len >> 2;
        const int tstep = 1024 / len;
        const int j  = bf & (q - 1);
        const int i0 = ((bf ^ j) << 2) | j;
        float2 w1 = tws[j * tstep];
        float2 w2 = tws[2 * j * tstep];
        float2 w3 = tws[3 * j * tstep];
        float u0r = zr[i0],         u0i = zi[i0];
        float a1r = zr[i0 + q],     a1i = zi[i0 + q];
        float a2r = zr[i0 + 2 * q], a2i = zi[i0 + 2 * q];
        float a3r = zr[i0 + 3 * q], a3i = zi[i0 + 3 * q];
        float u1r = a1r * w1.x - a1i * w1.y, u1i = a1r * w1.y + a1i * w1.x;
        float u2r = a2r * w2.x - a2i * w2.y, u2i = a2r * w2.y + a2i * w2.x;
        float u3r = a3r * w3.x - a3i * w3.y, u3i = a3r * w3.y + a3i * w3.x;
        float v0r = u0r + u2r, v0i = u0i + u2i;
        float v1r = u0r - u2r, v1i = u0i - u2i;
        float v2r = u1r + u3r, v2i = u1i + u3i;
        float v3r = u1i - u3i, v3i = u3r - u1r;          // -i*(u1-u3)
        zr[i0]         = v0r + v2r; zi[i0]         = v0i + v2i;
        zr[i0 + q]     = v1r + v3r; zi[i0 + q]     = v1i + v3i;
        zr[i0 + 2 * q] = v0r - v2r; zi[i0 + 2 * q] = v0i - v2i;
        zr[i0 + 3 * q] = v1r - v3r; zi[i0 + 3 * q] = v1i - v3i;
        __syncthreads();
    }

    // real-FFT unpack + power spectrum -> smem (per channel half)
    float* pwc = (tid < 256) ? pw[0] : pw[1];
    for (int k = (tid & 255); k <= 1024; k += 256) {
        int ka = k & 1023;
        int kb = (1024 - k) & 1023;
        float ar = zr[ka], ai = zi[ka];
        float br = zr[kb], bi = -zi[kb];
        float er  = 0.5f * (ar + br);
        float ei  = 0.5f * (ai + bi);
        float dr  = ar - br;
        float di  = ai - bi;
        float orr = 0.5f * di;
        float oi  = -0.5f * dr;
        float2 w  = g_tw2048[k];
        float xr2 = er + w.x * orr - w.y * oi;
        float xi2 = ei + w.x * oi + w.y * orr;
        pwc[k] = xr2 * xr2 + xi2 * xi2;
    }
    __syncthreads();

    // banded mel projection: 2 threads per (m, ch), 48 taps each, shuffle-combine
    const int pair = tid >> 1;          // 0..255
    const int half = tid & 1;
    const int m    = pair & 127;
    const int ch   = pair >> 7;
    const int lo   = g_lo[m];
    const float* bd = g_band + m * BW;
    const float* pr = pw[ch] + lo;
    const int off = half * (BW / 2);
    float acc = 0.0f;
#pragma unroll
    for (int i = 0; i < BW / 2; i++) acc = fmaf(bd[off + i], pr[off + i], acc);
    acc += __shfl_xor_sync(0xffffffffu, acc, 1);
    if (half == 0)
        out[(((size_t)b * N_MELS + m) * T_FRAMES + t) * 2 + ch] = acc;
}

// ---------------- entry point ----------------
extern "C" void kernel_launch(void* const* d_in, const int* in_sizes, int n_in,
                              void* d_out, int out_size) {
    const float* x  = (const float*)d_in[0];   // (8, 661500, 2) f32
    const float* fb = (const float*)d_in[1];   // (128, 1025)   f32
    float* out = (float*)d_out;                // (8, 128, 1292, 2) f32

    init_misc<<<8, 256>>>();
    init_band<<<N_MELS, 256>>>(fb);
    fft_mel_kernel<<<dim3(T_FRAMES, 8), 512>>>(x, out);
}

// round 3
// speedup vs baseline: 1.7372x; 1.7372x over previous
#include <cuda_runtime.h>
#include <cuda_bf16.h>

// ---------------- problem constants ----------------
#define S_LEN    661500
#define HOP      512
#define N_HALF   1024
#define T_FRAMES 1292
#define NFRAMES  (16 * T_FRAMES)   // 20672 frame-channels
#define N_BINS   1025
#define KP       1040              // padded power row stride
#define N_MELS   128
#define BW       64                // mel band width (max real ~54)
#define MEL_FPB  8                 // frames per mel block (20672 = 8*2584)

// ---------------- device statics ----------------
__device__ float  g_power[(size_t)NFRAMES * KP];
__device__ float  g_bandT[BW * N_MELS];   // [tap][mel] transposed, zero padded
__device__ int    g_lo[N_MELS];
__device__ float  g_win[2048];
__device__ float2 g_tw1024[512];
__device__ float2 g_tw2048[1025];

// ---------------- init: window + twiddles ----------------
__global__ void init_misc() {
    int i = blockIdx.x * blockDim.x + threadIdx.x;
    if (i < 2048) g_win[i] = 0.5f - 0.5f * cospif((float)i / 1024.0f);
    if (i < 512) {
        float s, c; sincospif(-(float)i / 512.0f, &s, &c);
        g_tw1024[i] = make_float2(c, s);
    }
    if (i < 1025) {
        float s, c; sincospif(-(float)i / 1024.0f, &s, &c);
        g_tw2048[i] = make_float2(c, s);
    }
}

// ---------------- init: compact nonzero band per mel row (transposed) ----------------
__global__ void init_band(const float* __restrict__ fb) {
    __shared__ int slo, shi;
    const int m = blockIdx.x;
    const int tid = threadIdx.x;
    if (tid == 0) { slo = N_BINS; shi = -1; }
    __syncthreads();
    int l = N_BINS, h = -1;
    for (int k = tid; k < N_BINS; k += blockDim.x) {
        if (fb[m * N_BINS + k] != 0.0f) { l = min(l, k); h = max(h, k); }
    }
    atomicMin(&slo, l);
    atomicMax(&shi, h);
    __syncthreads();
    const int lo = (shi >= 0) ? slo : 0;
    for (int i = tid; i < BW; i += blockDim.x) {
        int k = lo + i;
        g_bandT[i * N_MELS + m] = (k <= shi && k < N_BINS) ? fb[m * N_BINS + k] : 0.0f;
    }
    if (tid == 0) g_lo[m] = lo;
}

// ---------------- per-frame windowed rFFT -> power spectrum ----------------
// R1-proven radix-2 kernel; len=2 stage fused into the bit-reversed load.
__global__ __launch_bounds__(256) void fft_power_kernel(const float* __restrict__ x) {
    __shared__ float  zr[N_HALF];
    __shared__ float  zi[N_HALF];
    __shared__ float2 tw[512];

    const int tid = threadIdx.x;
    const int f   = blockIdx.x;
    const int g   = f / T_FRAMES;
    const int t   = f - g * T_FRAMES;
    const int b   = g >> 1;
    const int c   = g & 1;
    const float* xb = x + (size_t)b * S_LEN * 2 + c;

    for (int i = tid; i < 512; i += 256) tw[i] = g_tw1024[i];

    // reflect-pad + window; pack reals pairwise; fuse the w=1 (len=2) butterfly:
    // z[k] and z[k+512] land at adjacent bit-reversed slots r, r+1.
    const int base = t * HOP - 1024;
    for (int k = tid; k < 512; k += 256) {
#pragma unroll
        // element A = z[k], element B = z[k+512]
        int n0 = 2 * k;
        int pa0 = base + n0,         pa1 = base + n0 + 1;
        int pb0 = base + n0 + 1024,  pb1 = base + n0 + 1025;
        pa0 = (pa0 < 0) ? -pa0 : ((pa0 >= S_LEN) ? 2 * S_LEN - 2 - pa0 : pa0);
        pa1 = (pa1 < 0) ? -pa1 : ((pa1 >= S_LEN) ? 2 * S_LEN - 2 - pa1 : pa1);
        pb0 = (pb0 < 0) ? -pb0 : ((pb0 >= S_LEN) ? 2 * S_LEN - 2 - pb0 : pb0);
        pb1 = (pb1 < 0) ? -pb1 : ((pb1 >= S_LEN) ? 2 * S_LEN - 2 - pb1 : pb1);
        float ar = g_win[n0]        * xb[(size_t)pa0 * 2];
        float ai = g_win[n0 + 1]    * xb[(size_t)pa1 * 2];
        float br = g_win[n0 + 1024] * xb[(size_t)pb0 * 2];
        float bi = g_win[n0 + 1025] * xb[(size_t)pb1 * 2];
        unsigned r = __brev((unsigned)k) >> 22;   // k<512 -> bit9=0 -> r even
        *(float2*)&zr[r] = make_float2(ar + br, ar - br);
        *(float2*)&zi[r] = make_float2(ai + bi, ai - bi);
    }
    __syncthreads();

    // radix-2 DIT stages, len = 4 .. 1024
    for (int len = 4; len <= N_HALF; len <<= 1) {
        const int half  = len >> 1;
        const int tstep = N_HALF / len;
        for (int bf = tid; bf < (N_HALF / 2); bf += 256) {
            int j  = bf & (half - 1);
            int i0 = ((bf ^ j) << 1) | j;
            int i1 = i0 + half;
            float2 w = tw[j * tstep];
            float xr = zr[i1], xi = zi[i1];
            float tr = w.x * xr - w.y * xi;
            float ti = w.x * xi + w.y * xr;
            float ur = zr[i0], ui = zi[i0];
            zr[i1] = ur - tr; zi[i1] = ui - ti;
            zr[i0] = ur + tr; zi[i0] = ui + ti;
        }
        __syncthreads();
    }

    // real-FFT unpack + power, bins 0..1024; zero pad to KP
    float* pr = g_power + (size_t)f * KP;
    for (int k = tid; k <= N_HALF; k += 256) {
        int ka = k & (N_HALF - 1);
        int kb = (N_HALF - k) & (N_HALF - 1);
        float ar = zr[ka], ai = zi[ka];
        float br = zr[kb], bi = -zi[kb];
        float er  = 0.5f * (ar + br);
        float ei  = 0.5f * (ai + bi);
        float dr  = ar - br;
        float di  = ai - bi;
        float orr = 0.5f * di;
        float oi  = -0.5f * dr;
        float2 w = g_tw2048[k];
        float xr2 = er + w.x * orr - w.y * oi;
        float xi2 = ei + w.x * oi + w.y * orr;
        pr[k] = xr2 * xr2 + xi2 * xi2;
    }
    if (tid < (KP - N_BINS)) pr[N_BINS + tid] = 0.0f;
}

// ---------------- banded mel: 8 frames per block, band in registers ----------------
__global__ __launch_bounds__(128) void mel_band_kernel(float* __restrict__ out) {
    __shared__ float pw[MEL_FPB * KP];   // 8 x 1040 floats = 33.3 KB

    const int tid   = threadIdx.x;       // = mel index m
    const int fidx0 = blockIdx.x * MEL_FPB;

    // cooperative coalesced load of 8 power rows (float4)
    const float4* src = (const float4*)(g_power + (size_t)fidx0 * KP);
    float4* dst = (float4*)pw;
    for (int i = tid; i < MEL_FPB * KP / 4; i += 128) dst[i] = src[i];

    // band taps into registers (coalesced: lane m reads bandT[i][m])
    float bw[BW];
#pragma unroll
    for (int i = 0; i < BW; i++) bw[i] = g_bandT[i * N_MELS + tid];
    const int lo = g_lo[tid];
    __syncthreads();

#pragma unroll
    for (int ff = 0; ff < MEL_FPB; ff++) {
        const float* p = pw + ff * KP + lo;
        float a0 = 0.0f, a1 = 0.0f;
#pragma unroll
        for (int i = 0; i < BW; i += 2) {
            a0 = fmaf(bw[i],     p[i],     a0);
            a1 = fmaf(bw[i + 1], p[i + 1], a1);
        }
        int frame = fidx0 + ff;
        int g = frame / T_FRAMES;
        int t = frame - g * T_FRAMES;
        int b = g >> 1;
        int c = g & 1;
        out[(((size_t)b * N_MELS + tid) * T_FRAMES + t) * 2 + c] = a0 + a1;
    }
}

// ---------------- entry point ----------------
extern "C" void kernel_launch(void* const* d_in, const int* in_sizes, int n_in,
                              void* d_out, int out_size) {
    const float* x  = (const float*)d_in[0];   // (8, 661500, 2) f32
    const float* fb = (const float*)d_in[1];   // (128, 1025)   f32
    float* out = (float*)d_out;                // (8, 128, 1292, 2) f32

    init_misc<<<8, 256>>>();
    init_band<<<N_MELS, 256>>>(fb);
    fft_power_kernel<<<NFRAMES, 256>>>(x);
    mel_band_kernel<<<NFRAMES / MEL_FPB, 128>>>(out);
}

// round 4
// speedup vs baseline: 4.1142x; 2.3683x over previous
#include <cuda_runtime.h>
#include <cuda_bf16.h>

// ---------------- problem constants ----------------
#define S_LEN    661500
#define HOP      512
#define N_HALF   1024
#define T_FRAMES 1292
#define NFRAMES  (16 * T_FRAMES)   // 20672 frame-channels
#define N_BINS   1025
#define KP       1040              // padded power row stride
#define N_MELS   128
#define BW       64                // mel band width (max real ~54)
#define MEL_FPB  8                 // frames per mel block (20672 = 8*2584)

// smem skews (index units: float2)
#define SKD(i) ((i) + ((i) >> 4))  // data arrays
#define SKT(i) ((i) + ((i) >> 3))  // twiddle table

// ---------------- device statics ----------------
__device__ float  g_power[(size_t)NFRAMES * KP];
__device__ float  g_bandT[BW * N_MELS];   // [tap][mel] transposed, zero padded
__device__ int    g_lo[N_MELS];
__device__ float  g_win[2048];
__device__ float2 g_tw1024[512];          // W_1024^k (only k<256 used by stages)
__device__ float2 g_tw2048[1025];

// ---------------- init: window + twiddles ----------------
__global__ void init_misc() {
    int i = blockIdx.x * blockDim.x + threadIdx.x;
    if (i < 2048) g_win[i] = 0.5f - 0.5f * cospif((float)i / 1024.0f);
    if (i < 512) {
        float s, c; sincospif(-(float)i / 512.0f, &s, &c);
        g_tw1024[i] = make_float2(c, s);
    }
    if (i < 1025) {
        float s, c; sincospif(-(float)i / 1024.0f, &s, &c);
        g_tw2048[i] = make_float2(c, s);
    }
}

// ---------------- init: compact nonzero band per mel row (transposed) ----------------
__global__ void init_band(const float* __restrict__ fb) {
    __shared__ int slo, shi;
    const int m = blockIdx.x;
    const int tid = threadIdx.x;
    if (tid == 0) { slo = N_BINS; shi = -1; }
    __syncthreads();
    int l = N_BINS, h = -1;
    for (int k = tid; k < N_BINS; k += blockDim.x) {
        if (fb[m * N_BINS + k] != 0.0f) { l = min(l, k); h = max(h, k); }
    }
    atomicMin(&slo, l);
    atomicMax(&shi, h);
    __syncthreads();
    const int lo = (shi >= 0) ? slo : 0;
    for (int i = tid; i < BW; i += blockDim.x) {
        int k = lo + i;
        g_bandT[i * N_MELS + m] = (k <= shi && k < N_BINS) ? fb[m * N_BINS + k] : 0.0f;
    }
    if (tid == 0) g_lo[m] = lo;
}

// ---------------- one Stockham radix-4 stage ----------------
// Reads contiguous (conflict-free); writes strided (skew keeps <=2-way).
template<int L, int STEP, int LG>
__device__ __forceinline__ void fft_stage(const float2* __restrict__ src,
                                          float2* __restrict__ dst,
                                          const float2* __restrict__ tws, int j) {
    const int p = j & (L - 1);
    float2 a0 = src[SKD(j)];
    float2 a1 = src[SKD(j + 256)];
    float2 a2 = src[SKD(j + 512)];
    float2 a3 = src[SKD(j + 768)];
    float2 w1 = tws[SKT(p * STEP)];
    float w2r = w1.x * w1.x - w1.y * w1.y;          // w1^2
    float w2i = 2.0f * w1.x * w1.y;
    float w3r = w2r * w1.x - w2i * w1.y;            // w1^3
    float w3i = w2r * w1.y + w2i * w1.x;
    float u1r = a1.x * w1.x - a1.y * w1.y, u1i = a1.x * w1.y + a1.y * w1.x;
    float u2r = a2.x * w2r  - a2.y * w2i,  u2i = a2.x * w2i  + a2.y * w2r;
    float u3r = a3.x * w3r  - a3.y * w3i,  u3i = a3.x * w3i  + a3.y * w3r;
    float v0r = a0.x + u2r, v0i = a0.y + u2i;
    float v1r = a0.x - u2r, v1i = a0.y - u2i;
    float v2r = u1r + u3r,  v2i = u1i + u3i;
    float v3r = u1i - u3i,  v3i = u3r - u1r;        // -i*(u1-u3)
    const int o = ((j >> LG) << (LG + 2)) | p;      // q*4L + p
    dst[SKD(o)]         = make_float2(v0r + v2r, v0i + v2i);
    dst[SKD(o + L)]     = make_float2(v1r + v3r, v1i + v3i);
    dst[SKD(o + 2 * L)] = make_float2(v0r - v2r, v0i - v2i);
    dst[SKD(o + 3 * L)] = make_float2(v1r - v3r, v1i - v3i);
}

// ---------------- per-frame windowed rFFT -> power spectrum ----------------
__global__ __launch_bounds__(256) void fft_power_kernel(const float* __restrict__ x) {
    __shared__ float2 za[SKD(1023) + 2];   // 1088
    __shared__ float2 zb[SKD(1023) + 2];
    __shared__ float2 tws[SKT(255) + 2];   // 288

    const int j = threadIdx.x;
    const int f = blockIdx.x;
    const int g = f / T_FRAMES;
    const int t = f - g * T_FRAMES;
    const int b = g >> 1;
    const int c = g & 1;
    const float* xb = x + (size_t)b * S_LEN * 2 + c;
    const float2* win2 = (const float2*)g_win;

    if (j < 256) { /* all threads */ }
    if (j < 256) { }
    // stage twiddles (skewed)
    {
        int i = j;
        if (i < 256) tws[SKT(i)] = g_tw1024[i];
    }

    // fused load + stage 0 (L=1, twiddles unity): a_k = z[j + 256k] -> za[4j + k]
    {
        const int base = t * HOP - 1024;
        float zr[4], zi[4];
#pragma unroll
        for (int k = 0; k < 4; k++) {
            int n = j + 256 * k;
            int p0 = base + 2 * n;
            int p1 = p0 + 1;
            p0 = (p0 < 0) ? -p0 : ((p0 >= S_LEN) ? 2 * S_LEN - 2 - p0 : p0);
            p1 = (p1 < 0) ? -p1 : ((p1 >= S_LEN) ? 2 * S_LEN - 2 - p1 : p1);
            float2 w = __ldg(&win2[n]);
            zr[k] = w.x * __ldg(xb + (size_t)p0 * 2);
            zi[k] = w.y * __ldg(xb + (size_t)p1 * 2);
        }
        float v0r = zr[0] + zr[2], v0i = zi[0] + zi[2];
        float v1r = zr[0] - zr[2], v1i = zi[0] - zi[2];
        float v2r = zr[1] + zr[3], v2i = zi[1] + zi[3];
        float v3r = zi[1] - zi[3], v3i = zr[3] - zr[1];
        za[SKD(4 * j + 0)] = make_float2(v0r + v2r, v0i + v2i);
        za[SKD(4 * j + 1)] = make_float2(v1r + v3r, v1i + v3i);
        za[SKD(4 * j + 2)] = make_float2(v0r - v2r, v0i - v2i);
        za[SKD(4 * j + 3)] = make_float2(v1r - v3r, v1i - v3i);
    }
    __syncthreads();

    fft_stage<4, 64, 2>(za, zb, tws, j);   __syncthreads();
    fft_stage<16, 16, 4>(zb, za, tws, j);  __syncthreads();
    fft_stage<64, 4, 6>(za, zb, tws, j);   __syncthreads();
    fft_stage<256, 1, 8>(zb, za, tws, j);  __syncthreads();

    // real-FFT unpack + power, bins 0..1024; zero pad to KP
    float* pr = g_power + (size_t)f * KP;
    for (int k = j; k <= N_HALF; k += 256) {
        int ka = k & (N_HALF - 1);
        int kb = (N_HALF - k) & (N_HALF - 1);
        float2 A = za[SKD(ka)];
        float2 B = za[SKD(kb)];
        float ar = A.x, ai = A.y;
        float br = B.x, bi = -B.y;
        float er  = 0.5f * (ar + br);
        float ei  = 0.5f * (ai + bi);
        float dr  = ar - br;
        float di  = ai - bi;
        float orr = 0.5f * di;
        float oi  = -0.5f * dr;
        float2 w  = g_tw2048[k];
        float xr2 = er + w.x * orr - w.y * oi;
        float xi2 = ei + w.x * oi + w.y * orr;
        pr[k] = xr2 * xr2 + xi2 * xi2;
    }
    if (j < (KP - N_BINS)) pr[N_BINS + j] = 0.0f;
}

// ---------------- banded mel: 8 frames per block, band in registers ----------------
__global__ __launch_bounds__(128) void mel_band_kernel(float* __restrict__ out) {
    __shared__ float pw[MEL_FPB * KP];   // 8 x 1040 floats = 33.3 KB

    const int tid   = threadIdx.x;       // = mel index m
    const int fidx0 = blockIdx.x * MEL_FPB;

    const float4* src = (const float4*)(g_power + (size_t)fidx0 * KP);
    float4* dst = (float4*)pw;
#pragma unroll 4
    for (int i = tid; i < MEL_FPB * KP / 4; i += 128) dst[i] = src[i];

    float bw[BW];
#pragma unroll
    for (int i = 0; i < BW; i++) bw[i] = g_bandT[i * N_MELS + tid];
    const int lo = g_lo[tid];
    __syncthreads();

#pragma unroll
    for (int ff = 0; ff < MEL_FPB; ff++) {
        const float* p = pw + ff * KP + lo;
        float a0 = 0.0f, a1 = 0.0f, a2 = 0.0f, a3 = 0.0f;
#pragma unroll
        for (int i = 0; i < BW; i += 4) {
            a0 = fmaf(bw[i],     p[i],     a0);
            a1 = fmaf(bw[i + 1], p[i + 1], a1);
            a2 = fmaf(bw[i + 2], p[i + 2], a2);
            a3 = fmaf(bw[i + 3], p[i + 3], a3);
        }
        int frame = fidx0 + ff;
        int g = frame / T_FRAMES;
        int t = frame - g * T_FRAMES;
        int b = g >> 1;
        int c = g & 1;
        out[(((size_t)b * N_MELS + tid) * T_FRAMES + t) * 2 + c] = (a0 + a1) + (a2 + a3);
    }
}

// ---------------- entry point ----------------
extern "C" void kernel_launch(void* const* d_in, const int* in_sizes, int n_in,
                              void* d_out, int out_size) {
    const float* x  = (const float*)d_in[0];   // (8, 661500, 2) f32
    const float* fb = (const float*)d_in[1];   // (128, 1025)   f32
    float* out = (float*)d_out;                // (8, 128, 1292, 2) f32

    init_misc<<<8, 256>>>();
    init_band<<<N_MELS, 256>>>(fb);
    fft_power_kernel<<<NFRAMES, 256>>>(x);
    mel_band_kernel<<<NFRAMES / MEL_FPB, 128>>>(out);
}

// round 5
// speedup vs baseline: 5.2238x; 1.2697x over previous
#include <cuda_runtime.h>
#include <cuda_bf16.h>

// ---------------- problem constants ----------------
#define S_LEN    661500
#define HOP      512
#define NFFT     2048
#define T_FRAMES 1292
#define NFRAMES  (16 * T_FRAMES)   // 20672 frame-channels
#define N_BINS   1025
#define KP       1040              // padded power row stride
#define N_MELS   128
#define BW       64                // mel band width (max real ~54)
#define MEL_FPB  8                 // frames per mel block (20672 = 8*2584)

// smem skews (index units: float2)
#define SKD(i) ((i) + ((i) >> 4))  // data arrays
#define SKT(i) ((i) + ((i) >> 3))  // twiddle table

// ---------------- device statics ----------------
__device__ float  g_power[(size_t)NFRAMES * KP];
__device__ float  g_bandT[BW * N_MELS];   // [tap][mel] transposed, zero padded
__device__ int    g_lo[N_MELS];
__device__ int    g_nch[N_MELS];          // ceil(width/16), 1..4
__device__ float  g_win[NFFT];
__device__ float2 g_tw2048[1025];         // W_2048^k (stages use k<512)

// ---------------- init: window + twiddles ----------------
__global__ void init_misc() {
    int i = blockIdx.x * blockDim.x + threadIdx.x;
    if (i < NFFT) g_win[i] = 0.5f - 0.5f * cospif((float)i / 1024.0f);
    if (i < 1025) {
        float s, c; sincospif(-(float)i / 1024.0f, &s, &c);
        g_tw2048[i] = make_float2(c, s);
    }
}

// ---------------- init: compact nonzero band per mel row (transposed) ----------------
__global__ void init_band(const float* __restrict__ fb) {
    __shared__ int slo, shi;
    const int m = blockIdx.x;
    const int tid = threadIdx.x;
    if (tid == 0) { slo = N_BINS; shi = -1; }
    __syncthreads();
    int l = N_BINS, h = -1;
    for (int k = tid; k < N_BINS; k += blockDim.x) {
        if (fb[m * N_BINS + k] != 0.0f) { l = min(l, k); h = max(h, k); }
    }
    atomicMin(&slo, l);
    atomicMax(&shi, h);
    __syncthreads();
    const int lo = (shi >= 0) ? slo : 0;
    for (int i = tid; i < BW; i += blockDim.x) {
        int k = lo + i;
        g_bandT[i * N_MELS + m] = (k <= shi && k < N_BINS) ? fb[m * N_BINS + k] : 0.0f;
    }
    if (tid == 0) {
        g_lo[m] = lo;
        int w = (shi >= lo) ? (shi - lo + 1) : 1;
        if (w > BW) w = BW;
        g_nch[m] = (w + 15) >> 4;
    }
}

// ---------------- one Stockham radix-4 stage (N=2048, 2 butterflies/thread) ----------------
template<int L, int STEP, int LG>
__device__ __forceinline__ void fft_stage(const float2* __restrict__ src,
                                          float2* __restrict__ dst,
                                          const float2* __restrict__ tws, int j) {
#pragma unroll
    for (int h = 0; h < 2; h++) {
        const int bf = j + 256 * h;
        const int p  = bf & (L - 1);
        float2 a0 = src[SKD(bf)];
        float2 a1 = src[SKD(bf + 512)];
        float2 a2 = src[SKD(bf + 1024)];
        float2 a3 = src[SKD(bf + 1536)];
        float2 w1 = tws[SKT(p * STEP)];
        float w2r = w1.x * w1.x - w1.y * w1.y;        // w1^2
        float w2i = 2.0f * w1.x * w1.y;
        float w3r = w2r * w1.x - w2i * w1.y;          // w1^3
        float w3i = w2r * w1.y + w2i * w1.x;
        float u1r = a1.x * w1.x - a1.y * w1.y, u1i = a1.x * w1.y + a1.y * w1.x;
        float u2r = a2.x * w2r  - a2.y * w2i,  u2i = a2.x * w2i  + a2.y * w2r;
        float u3r = a3.x * w3r  - a3.y * w3i,  u3i = a3.x * w3i  + a3.y * w3r;
        float v0r = a0.x + u2r, v0i = a0.y + u2i;
        float v1r = a0.x - u2r, v1i = a0.y - u2i;
        float v2r = u1r + u3r,  v2i = u1i + u3i;
        float v3r = u1i - u3i,  v3i = u3r - u1r;      // -i*(u1-u3)
        const int o = ((bf >> LG) << (LG + 2)) | p;   // q*4L + p
        dst[SKD(o)]         = make_float2(v0r + v2r, v0i + v2i);
        dst[SKD(o + L)]     = make_float2(v1r + v3r, v1i + v3i);
        dst[SKD(o + 2 * L)] = make_float2(v0r - v2r, v0i - v2i);
        dst[SKD(o + 3 * L)] = make_float2(v1r - v3r, v1i - v3i);
    }
}

// ---------------- per-frame (both channels): windowed 2048-pt FFT -> 2 power rows ----------------
__global__ __launch_bounds__(256) void fft_power_kernel(const float* __restrict__ x) {
    __shared__ float2 za[SKD(2047) + 2];   // 2176 float2
    __shared__ float2 zb[SKD(2047) + 2];
    __shared__ float2 tws[SKT(511) + 2];   // ~576 float2

    const int j = threadIdx.x;
    const int t = blockIdx.x;
    const int b = blockIdx.y;
    const float2* xp = (const float2*)x + (size_t)b * S_LEN;  // (ch0, ch1)

    // stage twiddles (skewed)
    for (int i = j; i < 512; i += 256) tws[SKT(i)] = g_tw2048[i];

    // fused load + radix-2 stage (L=1): z[n] = win[n]*(x0 + i*x1), pairs (n, n+1024)
    {
        const int base = t * HOP - 1024;
#pragma unroll
        for (int k = 0; k < 4; k++) {
            int n  = j + 256 * k;
            int pa = base + n;
            int pb = pa + 1024;
            pa = (pa < 0) ? -pa : ((pa >= S_LEN) ? 2 * S_LEN - 2 - pa : pa);
            pb = (pb < 0) ? -pb : ((pb >= S_LEN) ? 2 * S_LEN - 2 - pb : pb);
            float2 va = __ldg(&xp[pa]);
            float2 vb = __ldg(&xp[pb]);
            float  wa = g_win[n];
            float  wb = g_win[n + 1024];
            float ur = wa * va.x, ui = wa * va.y;
            float vr = wb * vb.x, vi = wb * vb.y;
            za[SKD(2 * n)]     = make_float2(ur + vr, ui + vi);
            za[SKD(2 * n + 1)] = make_float2(ur - vr, ui - vi);
        }
    }
    __syncthreads();

    fft_stage<2, 256, 1>(za, zb, tws, j);  __syncthreads();
    fft_stage<8, 64, 3>(zb, za, tws, j);   __syncthreads();
    fft_stage<32, 16, 5>(za, zb, tws, j);  __syncthreads();
    fft_stage<128, 4, 7>(zb, za, tws, j);  __syncthreads();
    fft_stage<512, 1, 9>(za, zb, tws, j);  __syncthreads();

    // two-real-signal unpack + power: A = (Z[k]+conj(Z[N-k]))/2, B = -i(Z[k]-conj(Z[N-k]))/2
    float* pr0 = g_power + (size_t)(b * 2 * T_FRAMES + t) * KP;           // channel 0
    float* pr1 = g_power + (size_t)((b * 2 + 1) * T_FRAMES + t) * KP;     // channel 1
    for (int k = j; k <= 1024; k += 256) {
        float2 Zk = zb[SKD(k)];
        float2 Zn = zb[SKD((NFFT - k) & (NFFT - 1))];
        float sr = Zk.x + Zn.x, si = Zk.y - Zn.y;   // 2*A
        float dr = Zk.x - Zn.x, di = Zk.y + Zn.y;   // Z[k]-conj(Z[N-k]); 2*B = (di, -dr)
        pr0[k] = 0.25f * (sr * sr + si * si);
        pr1[k] = 0.25f * (di * di + dr * dr);
    }
    if (j < (KP - N_BINS)) {
        pr0[N_BINS + j] = 0.0f;
        pr1[N_BINS + j] = 0.0f;
    }
}

// ---------------- banded mel: 8 frames per block, band in registers ----------------
__global__ __launch_bounds__(128) void mel_band_kernel(float* __restrict__ out) {
    __shared__ float pw[MEL_FPB * KP];   // 33.3 KB

    const int tid   = threadIdx.x;       // = mel index m
    const int fidx0 = blockIdx.x * MEL_FPB;

    const float4* src = (const float4*)(g_power + (size_t)fidx0 * KP);
    float4* dst = (float4*)pw;
#pragma unroll 4
    for (int i = tid; i < MEL_FPB * KP / 4; i += 128) dst[i] = src[i];

    float bw[BW];
#pragma unroll
    for (int i = 0; i < BW; i++) bw[i] = g_bandT[i * N_MELS + tid];
    const int lo = g_lo[tid];
    const int umax = __reduce_max_sync(0xffffffffu, g_nch[tid]);  // warp-uniform chunks
    __syncthreads();

#define MEL_DOT(TAPS)                                                          \
    {                                                                          \
        _Pragma("unroll")                                                      \
        for (int ff = 0; ff < MEL_FPB; ff++) {                                 \
            const float* p = pw + ff * KP + lo;                                \
            float a0 = 0.0f, a1 = 0.0f, a2 = 0.0f, a3 = 0.0f;                  \
            _Pragma("unroll")                                                  \
            for (int i = 0; i < (TAPS); i += 4) {                              \
                a0 = fmaf(bw[i],     p[i],     a0);                            \
                a1 = fmaf(bw[i + 1], p[i + 1], a1);                            \
                a2 = fmaf(bw[i + 2], p[i + 2], a2);                            \
                a3 = fmaf(bw[i + 3], p[i + 3], a3);                            \
            }                                                                  \
            int frame = fidx0 + ff;                                            \
            int g = frame / T_FRAMES;                                          \
            int t = frame - g * T_FRAMES;                                      \
            int b = g >> 1;                                                    \
            int c = g & 1;                                                     \
            out[(((size_t)b * N_MELS + tid) * T_FRAMES + t) * 2 + c] =         \
                (a0 + a1) + (a2 + a3);                                         \
        }                                                                      \
    }

    switch (umax) {
        case 1: MEL_DOT(16); break;
        case 2: MEL_DOT(32); break;
        case 3: MEL_DOT(48); break;
        default: MEL_DOT(64); break;
    }
#undef MEL_DOT
}

// ---------------- entry point ----------------
extern "C" void kernel_launch(void* const* d_in, const int* in_sizes, int n_in,
                              void* d_out, int out_size) {
    const float* x  = (const float*)d_in[0];   // (8, 661500, 2) f32
    const float* fb = (const float*)d_in[1];   // (128, 1025)   f32
    float* out = (float*)d_out;                // (8, 128, 1292, 2) f32

    init_misc<<<8, 256>>>();
    init_band<<<N_MELS, 256>>>(fb);
    fft_power_kernel<<<dim3(T_FRAMES, 8), 256>>>(x);
    mel_band_kernel<<<NFRAMES / MEL_FPB, 128>>>(out);
}

// round 6
// speedup vs baseline: 5.6746x; 1.0863x over previous
#include <cuda_runtime.h>
#include <cuda_bf16.h>

// ---------------- problem constants ----------------
#define S_LEN    661500
#define HOP      512
#define NFFT     2048
#define T_FRAMES 1292
#define N_BINS   1025
#define N_MELS   128
#define BW       64                // mel band width (max real ~54)
#define PWS      1056              // smem power row stride (>= 1025+31 guard)

// smem skews (index units: float2)
#define SKD(i) ((i) + ((i) >> 4))  // data arrays
#define SKT(i) ((i) + ((i) >> 3))  // twiddle table

// ---------------- device statics ----------------
__device__ float  g_bandT[BW * N_MELS];   // [tap][mel] transposed, zero padded
__device__ int    g_lo[N_MELS];
__device__ int    g_nch[N_MELS];          // ceil(width/16), 1..4
__device__ float  g_win[NFFT];
__device__ float2 g_tw2048[1025];         // W_2048^k (stages use k<512)

// ---------------- init: band compaction (blocks 0..127) + window/twiddles (block 128) ----------------
__global__ void init_all(const float* __restrict__ fb) {
    const int tid = threadIdx.x;
    if (blockIdx.x == 128) {
        for (int i = tid; i < NFFT; i += 256)
            g_win[i] = 0.5f - 0.5f * cospif((float)i / 1024.0f);
        for (int i = tid; i < 1025; i += 256) {
            float s, c; sincospif(-(float)i / 1024.0f, &s, &c);
            g_tw2048[i] = make_float2(c, s);
        }
        return;
    }
    __shared__ int slo, shi;
    const int m = blockIdx.x;
    if (tid == 0) { slo = N_BINS; shi = -1; }
    __syncthreads();
    int l = N_BINS, h = -1;
    for (int k = tid; k < N_BINS; k += blockDim.x) {
        if (fb[m * N_BINS + k] != 0.0f) { l = min(l, k); h = max(h, k); }
    }
    atomicMin(&slo, l);
    atomicMax(&shi, h);
    __syncthreads();
    const int lo = (shi >= 0) ? slo : 0;
    for (int i = tid; i < BW; i += blockDim.x) {
        int k = lo + i;
        g_bandT[i * N_MELS + m] = (k <= shi && k < N_BINS) ? fb[m * N_BINS + k] : 0.0f;
    }
    if (tid == 0) {
        g_lo[m] = lo;
        int w = (shi >= lo) ? (shi - lo + 1) : 1;
        if (w > BW) w = BW;
        g_nch[m] = (w + 15) >> 4;
    }
}

// ---------------- one Stockham radix-4 stage (N=2048, 2 butterflies/thread) ----------------
template<int L, int STEP, int LG>
__device__ __forceinline__ void fft_stage(const float2* __restrict__ src,
                                          float2* __restrict__ dst,
                                          const float2* __restrict__ tws, int j) {
#pragma unroll
    for (int h = 0; h < 2; h++) {
        const int bf = j + 256 * h;
        const int p  = bf & (L - 1);
        float2 a0 = src[SKD(bf)];
        float2 a1 = src[SKD(bf + 512)];
        float2 a2 = src[SKD(bf + 1024)];
        float2 a3 = src[SKD(bf + 1536)];
        float2 w1 = tws[SKT(p * STEP)];
        float w2r = w1.x * w1.x - w1.y * w1.y;        // w1^2
        float w2i = 2.0f * w1.x * w1.y;
        float w3r = w2r * w1.x - w2i * w1.y;          // w1^3
        float w3i = w2r * w1.y + w2i * w1.x;
        float u1r = a1.x * w1.x - a1.y * w1.y, u1i = a1.x * w1.y + a1.y * w1.x;
        float u2r = a2.x * w2r  - a2.y * w2i,  u2i = a2.x * w2i  + a2.y * w2r;
        float u3r = a3.x * w3r  - a3.y * w3i,  u3i = a3.x * w3i  + a3.y * w3r;
        float v0r = a0.x + u2r, v0i = a0.y + u2i;
        float v1r = a0.x - u2r, v1i = a0.y - u2i;
        float v2r = u1r + u3r,  v2i = u1i + u3i;
        float v3r = u1i - u3i,  v3i = u3r - u1r;      // -i*(u1-u3)
        const int o = ((bf >> LG) << (LG + 2)) | p;   // q*4L + p
        dst[SKD(o)]         = make_float2(v0r + v2r, v0i + v2i);
        dst[SKD(o + L)]     = make_float2(v1r + v3r, v1i + v3i);
        dst[SKD(o + 2 * L)] = make_float2(v0r - v2r, v0i - v2i);
        dst[SKD(o + 3 * L)] = make_float2(v1r - v3r, v1i - v3i);
    }
}

// ---------------- fused: windowed 2048-pt FFT (both channels) + power + banded mel ----------------
__global__ __launch_bounds__(256) void fft_mel_kernel(const float* __restrict__ x,
                                                      float* __restrict__ out) {
    __shared__ float2 za[SKD(2047) + 2];   // 2176 float2; reused as power [2][PWS]
    __shared__ float2 zb[SKD(2047) + 2];
    __shared__ float2 tws[SKT(511) + 2];

    const int j = threadIdx.x;
    const int t = blockIdx.x;
    const int b = blockIdx.y;
    const float2* xp = (const float2*)x + (size_t)b * S_LEN;  // (ch0, ch1)

    // stage twiddles (skewed)
    for (int i = j; i < 512; i += 256) tws[SKT(i)] = g_tw2048[i];

    // fused load + radix-2 stage (L=1): z[n] = win[n]*(x0 + i*x1), pairs (n, n+1024)
    {
        const int base = t * HOP - 1024;
#pragma unroll
        for (int k = 0; k < 4; k++) {
            int n  = j + 256 * k;
            int pa = base + n;
            int pb = pa + 1024;
            pa = (pa < 0) ? -pa : ((pa >= S_LEN) ? 2 * S_LEN - 2 - pa : pa);
            pb = (pb < 0) ? -pb : ((pb >= S_LEN) ? 2 * S_LEN - 2 - pb : pb);
            float2 va = __ldg(&xp[pa]);
            float2 vb = __ldg(&xp[pb]);
            float  wa = g_win[n];
            float  wb = g_win[n + 1024];
            float ur = wa * va.x, ui = wa * va.y;
            float vr = wb * vb.x, vi = wb * vb.y;
            za[SKD(2 * n)]     = make_float2(ur + vr, ui + vi);
            za[SKD(2 * n + 1)] = make_float2(ur - vr, ui - vi);
        }
    }
    __syncthreads();

    fft_stage<2, 256, 1>(za, zb, tws, j);  __syncthreads();
    fft_stage<8, 64, 3>(zb, za, tws, j);   __syncthreads();
    fft_stage<32, 16, 5>(za, zb, tws, j);  __syncthreads();
    fft_stage<128, 4, 7>(zb, za, tws, j);  __syncthreads();
    fft_stage<512, 1, 9>(za, zb, tws, j);  __syncthreads();

    // two-real-signal unpack + power -> smem (za is dead; reuse as float pw[2][PWS])
    float* pw = (float*)za;
    for (int k = j; k <= 1024; k += 256) {
        float2 Zk = zb[SKD(k)];
        float2 Zn = zb[SKD((NFFT - k) & (NFFT - 1))];
        float sr = Zk.x + Zn.x, si = Zk.y - Zn.y;   // 2*A (ch0)
        float dr = Zk.x - Zn.x, di = Zk.y + Zn.y;   // 2*B = (di, -dr) (ch1)
        pw[k]       = 0.25f * (sr * sr + si * si);
        pw[PWS + k] = 0.25f * (di * di + dr * dr);
    }
    if (j < (PWS - N_BINS)) {               // zero NaN-guard tail (bins 1025..1055)
        pw[N_BINS + j]       = 0.0f;
        pw[PWS + N_BINS + j] = 0.0f;
    }
    __syncthreads();

    // banded mel: one (mel, ch) per thread; warps 0-3 -> ch0, 4-7 -> ch1
    const int ch = j >> 7;
    const int m  = j & 127;
    const float* p = pw + ch * PWS + g_lo[m];
    const float* bt = g_bandT + m;          // column m, row stride 128 (coalesced per warp)
    const int umax = __reduce_max_sync(0xffffffffu, g_nch[m]);
    float a0 = 0.0f, a1 = 0.0f, a2 = 0.0f, a3 = 0.0f;

#define MEL_DOT(TAPS)                                                   \
    _Pragma("unroll")                                                   \
    for (int i = 0; i < (TAPS); i += 4) {                               \
        a0 = fmaf(bt[(i)     * N_MELS], p[i],     a0);                  \
        a1 = fmaf(bt[(i + 1) * N_MELS], p[i + 1], a1);                  \
        a2 = fmaf(bt[(i + 2) * N_MELS], p[i + 2], a2);                  \
        a3 = fmaf(bt[(i + 3) * N_MELS], p[i + 3], a3);                  \
    }

    switch (umax) {
        case 1: MEL_DOT(16); break;
        case 2: MEL_DOT(32); break;
        case 3: MEL_DOT(48); break;
        default: MEL_DOT(64); break;
    }
#undef MEL_DOT

    out[(((size_t)b * N_MELS + m) * T_FRAMES + t) * 2 + ch] = (a0 + a1) + (a2 + a3);
}

// ---------------- entry point ----------------
extern "C" void kernel_launch(void* const* d_in, const int* in_sizes, int n_in,
                              void* d_out, int out_size) {
    const float* x  = (const float*)d_in[0];   // (8, 661500, 2) f32
    const float* fb = (const float*)d_in[1];   // (128, 1025)   f32
    float* out = (float*)d_out;                // (8, 128, 1292, 2) f32

    init_all<<<129, 256>>>(fb);
    fft_mel_kernel<<<dim3(T_FRAMES, 8), 256>>>(x, out);
}

// round 7
// speedup vs baseline: 6.8237x; 1.2025x over previous
#include <cuda_runtime.h>
#include <cuda_bf16.h>

// ---------------- problem constants ----------------
#define S_LEN    661500
#define HOP      512
#define NFFT     2048
#define T_FRAMES 1292
#define N_BINS   1025
#define N_MELS   128
#define BW       64                // mel band width (max real ~54)
#define PWS      1056              // smem power row stride (>= 1025+31 guard)

// smem skews (index units: float2)
#define SKD(i) ((i) + ((i) >> 4))  // data arrays
#define SKT(i) ((i) + ((i) >> 3))  // twiddle table

// ---------------- device statics ----------------
__device__ float  g_bandT[BW * N_MELS];   // [tap][mel] transposed, zero padded
__device__ int    g_lo[N_MELS];
__device__ int    g_nch[N_MELS];          // ceil(width/16), 1..4
__device__ float  g_win[NFFT];
__device__ float2 g_tw2048[1025];         // W_2048^k (stages use k<512)

// ---------------- init ----------------
__global__ void init_all(const float* __restrict__ fb) {
    const int tid = threadIdx.x;
    if (blockIdx.x == 128) {
        for (int i = tid; i < NFFT; i += 256)
            g_win[i] = 0.5f - 0.5f * cospif((float)i / 1024.0f);
        for (int i = tid; i < 1025; i += 256) {
            float s, c; sincospif(-(float)i / 1024.0f, &s, &c);
            g_tw2048[i] = make_float2(c, s);
        }
        return;
    }
    __shared__ int slo, shi;
    const int m = blockIdx.x;
    if (tid == 0) { slo = N_BINS; shi = -1; }
    __syncthreads();
    int l = N_BINS, h = -1;
    for (int k = tid; k < N_BINS; k += blockDim.x) {
        if (fb[m * N_BINS + k] != 0.0f) { l = min(l, k); h = max(h, k); }
    }
    atomicMin(&slo, l);
    atomicMax(&shi, h);
    __syncthreads();
    const int lo = (shi >= 0) ? slo : 0;
    for (int i = tid; i < BW; i += blockDim.x) {
        int k = lo + i;
        g_bandT[i * N_MELS + m] = (k <= shi && k < N_BINS) ? fb[m * N_BINS + k] : 0.0f;
    }
    if (tid == 0) {
        g_lo[m] = lo;
        int w = (shi >= lo) ? (shi - lo + 1) : 1;
        if (w > BW) w = BW;
        g_nch[m] = (w + 15) >> 4;
    }
}

// ---------------- complex helpers ----------------
__device__ __forceinline__ float2 cmul(float2 a, float2 b) {
    return make_float2(fmaf(a.x, b.x, -a.y * b.y), fmaf(a.x, b.y, a.y * b.x));
}
__device__ __forceinline__ float2 cadd(float2 a, float2 b) { return make_float2(a.x + b.x, a.y + b.y); }
__device__ __forceinline__ float2 csub(float2 a, float2 b) { return make_float2(a.x - b.x, a.y - b.y); }
__device__ __forceinline__ float2 cmulni(float2 a) { return make_float2(a.y, -a.x); }  // -i*a

// ---------------- radix-8 butterfly (DIT, natural m order) ----------------
__device__ __forceinline__ void bfly8(float2* a) {
    const float C = 0.70710678118654752f;
    // evens a0,a2,a4,a6 -> e ; odds a1,a3,a5,a7 -> o (each a 4-pt DFT)
    float2 s02 = cadd(a[0], a[4]), d02 = csub(a[0], a[4]);
    float2 s46 = cadd(a[2], a[6]), d46 = cmulni(csub(a[2], a[6]));
    float2 e0 = cadd(s02, s46), e2 = csub(s02, s46);
    float2 e1 = cadd(d02, d46), e3 = csub(d02, d46);
    float2 s13 = cadd(a[1], a[5]), d13 = csub(a[1], a[5]);
    float2 s57 = cadd(a[3], a[7]), d57 = cmulni(csub(a[3], a[7]));
    float2 o0 = cadd(s13, s57), o2 = csub(s13, s57);
    float2 o1 = cadd(d13, d57), o3 = csub(d13, d57);
    // twist odds by W8^m
    float2 t1 = make_float2(C * (o1.x + o1.y), C * (o1.y - o1.x));   // * (c - ci)
    float2 t2 = cmulni(o2);                                          // * -i
    float2 t3 = make_float2(C * (o3.y - o3.x), -C * (o3.x + o3.y));  // * (-c - ci)
    a[0] = cadd(e0, o0); a[4] = csub(e0, o0);
    a[1] = cadd(e1, t1); a[5] = csub(e1, t1);
    a[2] = cadd(e2, t2); a[6] = csub(e2, t2);
    a[3] = cadd(e3, t3); a[7] = csub(e3, t3);
}

// ---------------- Stockham radix-8 stage (1 butterfly/thread) ----------------
template<int L, int STEP, int LG>
__device__ __forceinline__ void fft8_stage(const float2* __restrict__ src,
                                           float2* __restrict__ dst,
                                           const float2* __restrict__ tws, int j) {
    const int p = j & (L - 1);
    float2 a[8];
#pragma unroll
    for (int k = 0; k < 8; k++) a[k] = src[SKD(j + 256 * k)];
    float2 w1 = tws[SKT(p * STEP)];
    float2 w2 = cmul(w1, w1);
    float2 w3 = cmul(w2, w1);
    float2 w4 = cmul(w2, w2);
    float2 w5 = cmul(w3, w2);
    float2 w6 = cmul(w3, w3);
    float2 w7 = cmul(w4, w3);
    a[1] = cmul(a[1], w1);
    a[2] = cmul(a[2], w2);
    a[3] = cmul(a[3], w3);
    a[4] = cmul(a[4], w4);
    a[5] = cmul(a[5], w5);
    a[6] = cmul(a[6], w6);
    a[7] = cmul(a[7], w7);
    bfly8(a);
    const int o = ((j >> LG) << (LG + 3)) | p;
#pragma unroll
    for (int m = 0; m < 8; m++) dst[SKD(o + m * L)] = a[m];
}

// ---------------- Stockham radix-4 stage (2 butterflies/thread) ----------------
template<int L, int STEP, int LG>
__device__ __forceinline__ void fft4_stage(const float2* __restrict__ src,
                                           float2* __restrict__ dst,
                                           const float2* __restrict__ tws, int j) {
#pragma unroll
    for (int h = 0; h < 2; h++) {
        const int bf = j + 256 * h;
        const int p  = bf & (L - 1);
        float2 a0 = src[SKD(bf)];
        float2 a1 = src[SKD(bf + 512)];
        float2 a2 = src[SKD(bf + 1024)];
        float2 a3 = src[SKD(bf + 1536)];
        float2 w1 = tws[SKT(p * STEP)];
        float2 w2 = cmul(w1, w1);
        float2 w3 = cmul(w2, w1);
        float2 u1 = cmul(a1, w1);
        float2 u2 = cmul(a2, w2);
        float2 u3 = cmul(a3, w3);
        float2 v0 = cadd(a0, u2), v1 = csub(a0, u2);
        float2 v2 = cadd(u1, u3), v3 = cmulni(csub(u1, u3));
        const int o = ((bf >> LG) << (LG + 2)) | p;
        dst[SKD(o)]         = cadd(v0, v2);
        dst[SKD(o + L)]     = cadd(v1, v3);
        dst[SKD(o + 2 * L)] = csub(v0, v2);
        dst[SKD(o + 3 * L)] = csub(v1, v3);
    }
}

// ---------------- fused: windowed 2048-pt FFT (both channels) + power + banded mel ----------------
__global__ __launch_bounds__(256) void fft_mel_kernel(const float* __restrict__ x,
                                                      float* __restrict__ out) {
    __shared__ float2 za[SKD(2047) + 2];   // reused as power [2][PWS] at the end
    __shared__ float2 zb[SKD(2047) + 2];
    __shared__ float2 tws[SKT(511) + 2];

    const int j = threadIdx.x;
    const int t = blockIdx.x;
    const int b = blockIdx.y;
    const float2* xp = (const float2*)x + (size_t)b * S_LEN;  // (ch0, ch1)

    for (int i = j; i < 512; i += 256) tws[SKT(i)] = g_tw2048[i];

    // fused load + radix-8 stage 0 (L=1, unit twiddles): a_k = z[j+256k] -> za[8j+m]
    {
        const int base = t * HOP - 1024;
        float2 a[8];
#pragma unroll
        for (int k = 0; k < 8; k++) {
            int n = j + 256 * k;
            int p = base + n;
            p = (p < 0) ? -p : ((p >= S_LEN) ? 2 * S_LEN - 2 - p : p);
            float2 v = __ldg(&xp[p]);
            float  w = g_win[n];
            a[k] = make_float2(w * v.x, w * v.y);   // z = win*(ch0 + i*ch1)
        }
        bfly8(a);
#pragma unroll
        for (int m = 0; m < 8; m++) za[SKD(8 * j + m)] = a[m];
    }
    __syncthreads();

    fft8_stage<8, 32, 3>(za, zb, tws, j);   __syncthreads();
    fft8_stage<64, 4, 6>(zb, za, tws, j);   __syncthreads();
    fft4_stage<512, 1, 9>(za, zb, tws, j);  __syncthreads();

    // two-real-signal unpack + power -> smem (za dead; reuse as float pw[2][PWS])
    float* pw = (float*)za;
    for (int k = j; k <= 1024; k += 256) {
        float2 Zk = zb[SKD(k)];
        float2 Zn = zb[SKD((NFFT - k) & (NFFT - 1))];
        float sr = Zk.x + Zn.x, si = Zk.y - Zn.y;   // 2*A (ch0)
        float dr = Zk.x - Zn.x, di = Zk.y + Zn.y;   // 2*B = (di, -dr) (ch1)
        pw[k]       = 0.25f * (sr * sr + si * si);
        pw[PWS + k] = 0.25f * (di * di + dr * dr);
    }
    if (j < (PWS - N_BINS)) {               // zero NaN-guard tail
        pw[N_BINS + j]       = 0.0f;
        pw[PWS + N_BINS + j] = 0.0f;
    }
    __syncthreads();

    // banded mel: one (mel, ch) per thread; warps 0-3 -> ch0, 4-7 -> ch1
    const int ch = j >> 7;
    const int m  = j & 127;
    const float* p  = pw + ch * PWS + g_lo[m];
    const float* bt = g_bandT + m;          // column m, row stride 128 (coalesced)
    const int umax = __reduce_max_sync(0xffffffffu, g_nch[m]);
    float a0 = 0.0f, a1 = 0.0f, a2 = 0.0f, a3 = 0.0f;

#define MEL_DOT(TAPS)                                                   \
    _Pragma("unroll")                                                   \
    for (int i = 0; i < (TAPS); i += 4) {                               \
        a0 = fmaf(bt[(i)     * N_MELS], p[i],     a0);                  \
        a1 = fmaf(bt[(i + 1) * N_MELS], p[i + 1], a1);                  \
        a2 = fmaf(bt[(i + 2) * N_MELS], p[i + 2], a2);                  \
        a3 = fmaf(bt[(i + 3) * N_MELS], p[i + 3], a3);                  \
    }

    switch (umax) {
        case 1: MEL_DOT(16); break;
        case 2: MEL_DOT(32); break;
        case 3: MEL_DOT(48); break;
        default: MEL_DOT(64); break;
    }
#undef MEL_DOT

    out[(((size_t)b * N_MELS + m) * T_FRAMES + t) * 2 + ch] = (a0 + a1) + (a2 + a3);
}

// ---------------- entry point ----------------
extern "C" void kernel_launch(void* const* d_in, const int* in_sizes, int n_in,
                              void* d_out, int out_size) {
    const float* x  = (const float*)d_in[0];   // (8, 661500, 2) f32
    const float* fb = (const float*)d_in[1];   // (128, 1025)   f32
    float* out = (float*)d_out;                // (8, 128, 1292, 2) f32

    init_all<<<129, 256>>>(fb);
    fft_mel_kernel<<<dim3(T_FRAMES, 8), 256>>>(x, out);
}

// round 8
// speedup vs baseline: 7.4582x; 1.0930x over previous
#include <cuda_runtime.h>
#include <cuda_bf16.h>

// ---------------- problem constants ----------------
#define S_LEN    661500
#define HOP      512
#define NFFT     2048
#define T_FRAMES 1292
#define N_BINS   1025
#define N_MELS   128
#define BW       64                // mel band width (max real ~54)
#define PWS      1056              // smem power row stride (>= 1025+31 guard)

// smem skews (index units: float2)
#define SKD(i) ((i) + ((i) >> 4))  // data arrays
#define SKT(i) ((i) + ((i) >> 3))  // twiddle table

// ---------------- device statics ----------------
__device__ float  g_bandT[BW * N_MELS];   // [tap][mel] transposed, zero padded
__device__ int    g_lo[N_MELS];
__device__ int    g_nch[N_MELS];          // ceil(width/16), 1..4
__device__ float  g_win[NFFT];
__device__ float2 g_tw2048[1025];         // W_2048^k (stages use k<512)

// ---------------- init ----------------
__global__ void init_all(const float* __restrict__ fb) {
    const int tid = threadIdx.x;
    if (blockIdx.x == 128) {
        for (int i = tid; i < NFFT; i += 256)
            g_win[i] = 0.5f - 0.5f * cospif((float)i / 1024.0f);
        for (int i = tid; i < 1025; i += 256) {
            float s, c; sincospif(-(float)i / 1024.0f, &s, &c);
            g_tw2048[i] = make_float2(c, s);
        }
        return;
    }
    __shared__ int slo, shi;
    const int m = blockIdx.x;
    if (tid == 0) { slo = N_BINS; shi = -1; }
    __syncthreads();
    int l = N_BINS, h = -1;
    for (int k = tid; k < N_BINS; k += blockDim.x) {
        if (fb[m * N_BINS + k] != 0.0f) { l = min(l, k); h = max(h, k); }
    }
    atomicMin(&slo, l);
    atomicMax(&shi, h);
    __syncthreads();
    const int lo = (shi >= 0) ? slo : 0;
    for (int i = tid; i < BW; i += blockDim.x) {
        int k = lo + i;
        g_bandT[i * N_MELS + m] = (k <= shi && k < N_BINS) ? fb[m * N_BINS + k] : 0.0f;
    }
    if (tid == 0) {
        g_lo[m] = lo;
        int w = (shi >= lo) ? (shi - lo + 1) : 1;
        if (w > BW) w = BW;
        g_nch[m] = (w + 15) >> 4;
    }
}

// ---------------- complex helpers ----------------
__device__ __forceinline__ float2 cmul(float2 a, float2 b) {
    return make_float2(fmaf(a.x, b.x, -a.y * b.y), fmaf(a.x, b.y, a.y * b.x));
}
__device__ __forceinline__ float2 cadd(float2 a, float2 b) { return make_float2(a.x + b.x, a.y + b.y); }
__device__ __forceinline__ float2 csub(float2 a, float2 b) { return make_float2(a.x - b.x, a.y - b.y); }
__device__ __forceinline__ float2 cmulni(float2 a) { return make_float2(a.y, -a.x); }  // -i*a

// ---------------- radix-8 butterfly (DIT, natural m order) ----------------
__device__ __forceinline__ void bfly8(float2* a) {
    const float C = 0.70710678118654752f;
    float2 s02 = cadd(a[0], a[4]), d02 = csub(a[0], a[4]);
    float2 s46 = cadd(a[2], a[6]), d46 = cmulni(csub(a[2], a[6]));
    float2 e0 = cadd(s02, s46), e2 = csub(s02, s46);
    float2 e1 = cadd(d02, d46), e3 = csub(d02, d46);
    float2 s13 = cadd(a[1], a[5]), d13 = csub(a[1], a[5]);
    float2 s57 = cadd(a[3], a[7]), d57 = cmulni(csub(a[3], a[7]));
    float2 o0 = cadd(s13, s57), o2 = csub(s13, s57);
    float2 o1 = cadd(d13, d57), o3 = csub(d13, d57);
    float2 t1 = make_float2(C * (o1.x + o1.y), C * (o1.y - o1.x));   // * (c - ci)
    float2 t2 = cmulni(o2);                                          // * -i
    float2 t3 = make_float2(C * (o3.y - o3.x), -C * (o3.x + o3.y));  // * (-c - ci)
    a[0] = cadd(e0, o0); a[4] = csub(e0, o0);
    a[1] = cadd(e1, t1); a[5] = csub(e1, t1);
    a[2] = cadd(e2, t2); a[6] = csub(e2, t2);
    a[3] = cadd(e3, t3); a[7] = csub(e3, t3);
}

// ---------------- Stockham radix-8 stage (1 butterfly/thread) ----------------
template<int L, int STEP, int LG>
__device__ __forceinline__ void fft8_stage(const float2* __restrict__ src,
                                           float2* __restrict__ dst,
                                           const float2* __restrict__ tws, int j) {
    const int p = j & (L - 1);
    float2 a[8];
#pragma unroll
    for (int k = 0; k < 8; k++) a[k] = src[SKD(j + 256 * k)];
    float2 w1 = tws[SKT(p * STEP)];
    float2 w2 = cmul(w1, w1);
    float2 w3 = cmul(w2, w1);
    float2 w4 = cmul(w2, w2);
    float2 w5 = cmul(w3, w2);
    float2 w6 = cmul(w3, w3);
    float2 w7 = cmul(w4, w3);
    a[1] = cmul(a[1], w1);
    a[2] = cmul(a[2], w2);
    a[3] = cmul(a[3], w3);
    a[4] = cmul(a[4], w4);
    a[5] = cmul(a[5], w5);
    a[6] = cmul(a[6], w6);
    a[7] = cmul(a[7], w7);
    bfly8(a);
    const int o = ((j >> LG) << (LG + 3)) | p;
#pragma unroll
    for (int m = 0; m < 8; m++) dst[SKD(o + m * L)] = a[m];
}

// ---------------- final radix-4 butterfly (L=512): returns Z[bf + 512m] ----------------
__device__ __forceinline__ void fft4_final(const float2* __restrict__ src,
                                           const float2* __restrict__ tws,
                                           int bf, float2* Z) {
    float2 a0 = src[SKD(bf)];
    float2 a1 = src[SKD(bf + 512)];
    float2 a2 = src[SKD(bf + 1024)];
    float2 a3 = src[SKD(bf + 1536)];
    float2 w1 = tws[SKT(bf)];
    float2 w2 = cmul(w1, w1);
    float2 w3 = cmul(w2, w1);
    float2 u1 = cmul(a1, w1);
    float2 u2 = cmul(a2, w2);
    float2 u3 = cmul(a3, w3);
    float2 v0 = cadd(a0, u2), v1 = csub(a0, u2);
    float2 v2 = cadd(u1, u3), v3 = cmulni(csub(u1, u3));
    Z[0] = cadd(v0, v2);
    Z[1] = cadd(v1, v3);
    Z[2] = csub(v0, v2);
    Z[3] = csub(v1, v3);
}

// ---------------- fused: windowed 2048-pt FFT (both channels) + power + banded mel ----------------
__global__ __launch_bounds__(256) void fft_mel_kernel(const float* __restrict__ x,
                                                      float* __restrict__ out) {
    __shared__ float2 za[SKD(2047) + 2];
    __shared__ float2 zb[SKD(2047) + 2];   // reused as power [2][PWS] at the end
    __shared__ float2 tws[SKT(511) + 2];

    const int j = threadIdx.x;
    const int t = blockIdx.x;
    const int b = blockIdx.y;
    const float2* xp = (const float2*)x + (size_t)b * S_LEN;  // (ch0, ch1)

    for (int i = j; i < 512; i += 256) tws[SKT(i)] = g_tw2048[i];

    // fused load + radix-8 stage 0 (L=1, unit twiddles): a_k = z[j+256k] -> za[8j+m]
    {
        const int base = t * HOP - 1024;
        float2 a[8];
#pragma unroll
        for (int k = 0; k < 8; k++) {
            int n = j + 256 * k;
            int p = base + n;
            p = (p < 0) ? -p : ((p >= S_LEN) ? 2 * S_LEN - 2 - p : p);
            float2 v = __ldg(&xp[p]);
            float  w = g_win[n];
            a[k] = make_float2(w * v.x, w * v.y);   // z = win*(ch0 + i*ch1)
        }
        bfly8(a);
#pragma unroll
        for (int m = 0; m < 8; m++) za[SKD(8 * j + m)] = a[m];
    }
    __syncthreads();

    fft8_stage<8, 32, 3>(za, zb, tws, j);   __syncthreads();
    fft8_stage<64, 4, 6>(zb, za, tws, j);   __syncthreads();
    // (zb is dead from here: all reads completed before the last barrier)

    // fused final radix-4 stage + two-real unpack + power -> pw (aliases zb)
    float* pw = (float*)zb;
    {
        const int bf0 = j;
        const int bf1 = (j == 0) ? 256 : 512 - j;
        float2 ZA[4], ZB[4];
        fft4_final(za, tws, bf0, ZA);       // ZA[m] = Z[bf0 + 512m]
        fft4_final(za, tws, bf1, ZB);       // ZB[m] = Z[bf1 + 512m]

#define PWR(K, ZK, ZN)                                                  \
        {                                                               \
            float sr = (ZK).x + (ZN).x, si = (ZK).y - (ZN).y;           \
            float dr = (ZK).x - (ZN).x, di = (ZK).y + (ZN).y;           \
            pw[(K)]       = 0.25f * (sr * sr + si * si);                \
            pw[PWS + (K)] = 0.25f * (di * di + dr * dr);                \
        }
        if (j == 0) {
            PWR(0,    ZA[0], ZA[0]);        // Z[0] self-conjugate
            PWR(512,  ZA[1], ZA[3]);        // Z[512], Z[1536]
            PWR(1024, ZA[2], ZA[2]);        // Z[1024] self-conjugate
            PWR(256,  ZB[0], ZB[3]);        // Z[256], Z[1792]
            PWR(768,  ZB[1], ZB[2]);        // Z[768], Z[1280]
        } else {
            PWR(j,        ZA[0], ZB[3]);    // Z[j],      Z[2048-j]
            PWR(j + 512,  ZA[1], ZB[2]);    // Z[j+512],  Z[1536-j]
            PWR(512 - j,  ZB[0], ZA[3]);    // Z[512-j],  Z[1536+j]
            PWR(1024 - j, ZB[1], ZA[2]);    // Z[1024-j], Z[1024+j]
        }
#undef PWR
    }
    if (j < (PWS - N_BINS)) {               // zero NaN-guard tail (bins 1025..1055)
        pw[N_BINS + j]       = 0.0f;
        pw[PWS + N_BINS + j] = 0.0f;
    }
    __syncthreads();

    // banded mel: one (mel, ch) per thread; warps 0-3 -> ch0, 4-7 -> ch1
    const int ch = j >> 7;
    const int m  = j & 127;
    const float* p  = pw + ch * PWS + g_lo[m];
    const float* bt = g_bandT + m;          // column m, row stride 128 (coalesced)
    const int umax = __reduce_max_sync(0xffffffffu, g_nch[m]);
    float a0 = 0.0f, a1 = 0.0f, a2 = 0.0f, a3 = 0.0f;

#define MEL_DOT(TAPS)                                                   \
    _Pragma("unroll")                                                   \
    for (int i = 0; i < (TAPS); i += 4) {                               \
        a0 = fmaf(bt[(i)     * N_MELS], p[i],     a0);                  \
        a1 = fmaf(bt[(i + 1) * N_MELS], p[i + 1], a1);                  \
        a2 = fmaf(bt[(i + 2) * N_MELS], p[i + 2], a2);                  \
        a3 = fmaf(bt[(i + 3) * N_MELS], p[i + 3], a3);                  \
    }

    switch (umax) {
        case 1: MEL_DOT(16); break;
        case 2: MEL_DOT(32); break;
        case 3: MEL_DOT(48); break;
        default: MEL_DOT(64); break;
    }
#undef MEL_DOT

    out[(((size_t)b * N_MELS + m) * T_FRAMES + t) * 2 + ch] = (a0 + a1) + (a2 + a3);
}

// ---------------- entry point ----------------
extern "C" void kernel_launch(void* const* d_in, const int* in_sizes, int n_in,
                              void* d_out, int out_size) {
    const float* x  = (const float*)d_in[0];   // (8, 661500, 2) f32
    const float* fb = (const float*)d_in[1];   // (128, 1025)   f32
    float* out = (float*)d_out;                // (8, 128, 1292, 2) f32

    init_all<<<129, 256>>>(fb);
    fft_mel_kernel<<<dim3(T_FRAMES, 8), 256>>>(x, out);
}

// round 9
// speedup vs baseline: 8.4911x; 1.1385x over previous
#include <cuda_runtime.h>
#include <cuda_bf16.h>

// ---------------- problem constants ----------------
#define S_LEN    661500
#define HOP      512
#define NFFT     2048
#define T_FRAMES 1292
#define N_BINS   1025
#define N_MELS   128
#define BW       64                // mel band width (max real ~54)
#define PWS      1056              // smem power row stride (>= 1025+31 guard)

// smem skews (index units: float2)
#define SKD(i) ((i) + ((i) >> 4))  // data arrays
#define SKT(i) ((i) + ((i) >> 3))  // twiddle table

#define A2  (SKD(2047) + 2)        // 2176 float2 per data array
#define TWN (SKT(511) + 2)         // 576 float2 twiddle table
#define SMEM_F2 (4 * A2 + TWN)     // 2 frames x (za, zb) + twiddles
#define SMEM_BYTES (SMEM_F2 * 8)   // 74240

// ---------------- device statics ----------------
__device__ float  g_bandT[BW * N_MELS];   // [tap][mel] transposed, zero padded
__device__ int    g_lo[N_MELS];
__device__ int    g_nch[N_MELS];          // ceil(width/16), 1..4
__device__ float  g_win[NFFT];
__device__ float2 g_tw2048[1025];

// ---------------- init ----------------
__global__ void init_all(const float* __restrict__ fb) {
    const int tid = threadIdx.x;
    if (blockIdx.x == 128) {
        for (int i = tid; i < NFFT; i += 256)
            g_win[i] = 0.5f - 0.5f * cospif((float)i / 1024.0f);
        for (int i = tid; i < 1025; i += 256) {
            float s, c; sincospif(-(float)i / 1024.0f, &s, &c);
            g_tw2048[i] = make_float2(c, s);
        }
        return;
    }
    __shared__ int slo, shi;
    const int m = blockIdx.x;
    if (tid == 0) { slo = N_BINS; shi = -1; }
    __syncthreads();
    int l = N_BINS, h = -1;
    for (int k = tid; k < N_BINS; k += blockDim.x) {
        if (fb[m * N_BINS + k] != 0.0f) { l = min(l, k); h = max(h, k); }
    }
    atomicMin(&slo, l);
    atomicMax(&shi, h);
    __syncthreads();
    const int lo = (shi >= 0) ? slo : 0;
    for (int i = tid; i < BW; i += blockDim.x) {
        int k = lo + i;
        g_bandT[i * N_MELS + m] = (k <= shi && k < N_BINS) ? fb[m * N_BINS + k] : 0.0f;
    }
    if (tid == 0) {
        g_lo[m] = lo;
        int w = (shi >= lo) ? (shi - lo + 1) : 1;
        if (w > BW) w = BW;
        g_nch[m] = (w + 15) >> 4;
    }
}

// ---------------- complex helpers ----------------
__device__ __forceinline__ float2 cmul(float2 a, float2 b) {
    return make_float2(fmaf(a.x, b.x, -a.y * b.y), fmaf(a.x, b.y, a.y * b.x));
}
__device__ __forceinline__ float2 cadd(float2 a, float2 b) { return make_float2(a.x + b.x, a.y + b.y); }
__device__ __forceinline__ float2 csub(float2 a, float2 b) { return make_float2(a.x - b.x, a.y - b.y); }
__device__ __forceinline__ float2 cmulni(float2 a) { return make_float2(a.y, -a.x); }  // -i*a

// ---------------- radix-8 butterfly (DIT, natural order) ----------------
__device__ __forceinline__ void bfly8(float2* a) {
    const float C = 0.70710678118654752f;
    float2 s02 = cadd(a[0], a[4]), d02 = csub(a[0], a[4]);
    float2 s46 = cadd(a[2], a[6]), d46 = cmulni(csub(a[2], a[6]));
    float2 e0 = cadd(s02, s46), e2 = csub(s02, s46);
    float2 e1 = cadd(d02, d46), e3 = csub(d02, d46);
    float2 s13 = cadd(a[1], a[5]), d13 = csub(a[1], a[5]);
    float2 s57 = cadd(a[3], a[7]), d57 = cmulni(csub(a[3], a[7]));
    float2 o0 = cadd(s13, s57), o2 = csub(s13, s57);
    float2 o1 = cadd(d13, d57), o3 = csub(d13, d57);
    float2 t1 = make_float2(C * (o1.x + o1.y), C * (o1.y - o1.x));
    float2 t2 = cmulni(o2);
    float2 t3 = make_float2(C * (o3.y - o3.x), -C * (o3.x + o3.y));
    a[0] = cadd(e0, o0); a[4] = csub(e0, o0);
    a[1] = cadd(e1, t1); a[5] = csub(e1, t1);
    a[2] = cadd(e2, t2); a[6] = csub(e2, t2);
    a[3] = cadd(e3, t3); a[7] = csub(e3, t3);
}

// ---------------- radix-16 butterfly (4x4 Cooley-Tukey, natural order) ----------------
__device__ __forceinline__ void bfly16(float2* a) {
    const float C8 = 0.70710678118654752f;
    const float C1 = 0.92387953251128676f;   // cos(pi/8)
    const float S1 = 0.38268343236508977f;   // sin(pi/8)
    float2 B[4][4];
#pragma unroll
    for (int n2 = 0; n2 < 4; n2++) {
        float2 x0 = a[n2], x1 = a[n2 + 4], x2 = a[n2 + 8], x3 = a[n2 + 12];
        float2 t0 = cadd(x0, x2), t1 = csub(x0, x2);
        float2 t2 = cadd(x1, x3), t3 = cmulni(csub(x1, x3));
        B[n2][0] = cadd(t0, t2); B[n2][1] = cadd(t1, t3);
        B[n2][2] = csub(t0, t2); B[n2][3] = csub(t1, t3);
    }
    // inner twiddles W16^{n2*k1}
    B[1][1] = cmul(B[1][1], make_float2(C1, -S1));
    B[1][2] = cmul(B[1][2], make_float2(C8, -C8));
    B[1][3] = cmul(B[1][3], make_float2(S1, -C1));
    B[2][1] = cmul(B[2][1], make_float2(C8, -C8));
    B[2][2] = cmulni(B[2][2]);
    B[2][3] = cmul(B[2][3], make_float2(-C8, -C8));
    B[3][1] = cmul(B[3][1], make_float2(S1, -C1));
    B[3][2] = cmul(B[3][2], make_float2(-C8, -C8));
    B[3][3] = cmul(B[3][3], make_float2(-C1, S1));
#pragma unroll
    for (int k1 = 0; k1 < 4; k1++) {
        float2 x0 = B[0][k1], x1 = B[1][k1], x2 = B[2][k1], x3 = B[3][k1];
        float2 t0 = cadd(x0, x2), t1 = csub(x0, x2);
        float2 t2 = cadd(x1, x3), t3 = cmulni(csub(x1, x3));
        a[k1]      = cadd(t0, t2);
        a[k1 + 4]  = cadd(t1, t3);
        a[k1 + 8]  = csub(t0, t2);
        a[k1 + 12] = csub(t1, t3);
    }
}

// ---------------- final radix-8 butterfly (L=256): Z[m] = Z[bf + 256m] ----------------
__device__ __forceinline__ void fft8_final(const float2* __restrict__ src,
                                           const float2* __restrict__ tws,
                                           int bf, float2* Z) {
#pragma unroll
    for (int k = 0; k < 8; k++) Z[k] = src[SKD(bf + 256 * k)];
    float2 w1 = tws[SKT(bf)];
    float2 wk = w1;
    Z[1] = cmul(Z[1], wk);
#pragma unroll
    for (int k = 2; k < 8; k++) { wk = cmul(wk, w1); Z[k] = cmul(Z[k], wk); }
    bfly8(Z);
}

// ---------------- fused: 2 frames/block, radix-16/16/8 FFT + power + banded mel ----------------
__global__ __launch_bounds__(256) void fft_mel_kernel(const float* __restrict__ x,
                                                      float* __restrict__ out) {
    extern __shared__ float2 smem[];
    float2* tws = smem + 4 * A2;

    const int j  = threadIdx.x;
    const int f  = j >> 7;             // frame within block (0/1)
    const int jj = j & 127;
    const int t  = blockIdx.x * 2 + f;
    const int b  = blockIdx.y;
    const float2* xp = (const float2*)x + (size_t)b * S_LEN;  // (ch0, ch1)

    float2* za = smem + f * A2;
    float2* zb = smem + 2 * A2 + f * A2;

    for (int i = j; i < 512; i += 256) tws[SKT(i)] = g_tw2048[i];

    // fused load + radix-16 stage 0 (L=1, unit twiddles): a_k = z[jj+128k] -> za[16jj+m]
    {
        const int base = t * HOP - 1024;
        float2 a[16];
#pragma unroll
        for (int k = 0; k < 16; k++) {
            int n = jj + 128 * k;
            int p = base + n;
            p = (p < 0) ? -p : ((p >= S_LEN) ? 2 * S_LEN - 2 - p : p);
            float2 v = __ldg(&xp[p]);
            float  w = g_win[n];
            a[k] = make_float2(w * v.x, w * v.y);   // z = win*(ch0 + i*ch1)
        }
        bfly16(a);
#pragma unroll
        for (int m = 0; m < 16; m++) za[SKD(16 * jj + m)] = a[m];
    }
    __syncthreads();

    // radix-16 stage 1 (L=16, STEP=8): reads contiguous, incremental twiddle powers
    {
        const int p = jj & 15;
        float2 a[16];
#pragma unroll
        for (int k = 0; k < 16; k++) a[k] = za[SKD(jj + 128 * k)];
        float2 w1 = tws[SKT(p * 8)];
        float2 wk = w1;
        a[1] = cmul(a[1], wk);
#pragma unroll
        for (int k = 2; k < 16; k++) { wk = cmul(wk, w1); a[k] = cmul(a[k], wk); }
        bfly16(a);
        const int o = ((jj >> 4) << 8) | p;
#pragma unroll
        for (int m = 0; m < 16; m++) zb[SKD(o + 16 * m)] = a[m];
    }
    __syncthreads();

    // fused final radix-8 (L=256) + two-real unpack + power -> pw (aliases za)
    float* pw = (float*)za;
    {
        const int bf0 = jj;
        const int bf1 = (jj == 0) ? 128 : 256 - jj;
        float2 ZA[8], ZB[8];
        fft8_final(zb, tws, bf0, ZA);       // ZA[m] = Z[bf0 + 256m]
        fft8_final(zb, tws, bf1, ZB);       // ZB[m] = Z[bf1 + 256m]

#define PWR(K, ZK, ZN)                                                  \
        {                                                               \
            float sr = (ZK).x + (ZN).x, si = (ZK).y - (ZN).y;           \
            float dr = (ZK).x - (ZN).x, di = (ZK).y + (ZN).y;           \
            pw[(K)]       = 0.25f * (sr * sr + si * si);                \
            pw[PWS + (K)] = 0.25f * (di * di + dr * dr);                \
        }
        if (jj == 0) {
            PWR(0,    ZA[0], ZA[0]);
            PWR(256,  ZA[1], ZA[7]);
            PWR(512,  ZA[2], ZA[6]);
            PWR(768,  ZA[3], ZA[5]);
            PWR(1024, ZA[4], ZA[4]);
#pragma unroll
            for (int m = 0; m < 4; m++) PWR(128 + 256 * m, ZB[m], ZB[7 - m]);
        } else {
#pragma unroll
            for (int m = 0; m < 4; m++) {
                PWR(jj + 256 * m,         ZA[m], ZB[7 - m]);   // Z[k], Z[2048-k]
                PWR((256 - jj) + 256 * m, ZB[m], ZA[7 - m]);
            }
        }
#undef PWR
    }
    if (jj < (PWS - N_BINS)) {              // zero NaN-guard tail (bins 1025..1055)
        pw[N_BINS + jj]       = 0.0f;
        pw[PWS + N_BINS + jj] = 0.0f;
    }
    __syncthreads();

    // banded mel: thread j -> mel m = j&127, channel ch = j>>7, BOTH frames
    const int ch = j >> 7;
    const int m  = j & 127;
    const int lo = g_lo[m];
    const float* p0 = (const float*)(smem)      + ch * PWS + lo;   // frame 0 power
    const float* p1 = (const float*)(smem + A2) + ch * PWS + lo;   // frame 1 power
    const float* bt = g_bandT + m;          // column m, row stride 128 (coalesced)
    const int umax = __reduce_max_sync(0xffffffffu, g_nch[m]);
    float q0 = 0.0f, q1 = 0.0f, q2 = 0.0f, q3 = 0.0f;   // frame 0
    float r0 = 0.0f, r1 = 0.0f, r2 = 0.0f, r3 = 0.0f;   // frame 1

#define MEL_DOT(TAPS)                                                   \
    _Pragma("unroll")                                                   \
    for (int i = 0; i < (TAPS); i += 4) {                               \
        float b0 = bt[(i)     * N_MELS];                                \
        float b1 = bt[(i + 1) * N_MELS];                                \
        float b2 = bt[(i + 2) * N_MELS];                                \
        float b3 = bt[(i + 3) * N_MELS];                                \
        q0 = fmaf(b0, p0[i],     q0);  r0 = fmaf(b0, p1[i],     r0);    \
        q1 = fmaf(b1, p0[i + 1], q1);  r1 = fmaf(b1, p1[i + 1], r1);    \
        q2 = fmaf(b2, p0[i + 2], q2);  r2 = fmaf(b2, p1[i + 2], r2);    \
        q3 = fmaf(b3, p0[i + 3], q3);  r3 = fmaf(b3, p1[i + 3], r3);    \
    }

    switch (umax) {
        case 1: MEL_DOT(16); break;
        case 2: MEL_DOT(32); break;
        case 3: MEL_DOT(48); break;
        default: MEL_DOT(64); break;
    }
#undef MEL_DOT

    const size_t obase = (((size_t)b * N_MELS + m) * T_FRAMES + blockIdx.x * 2) * 2 + ch;
    out[obase]     = (q0 + q1) + (q2 + q3);
    out[obase + 2] = (r0 + r1) + (r2 + r3);
}

// ---------------- entry point ----------------
extern "C" void kernel_launch(void* const* d_in, const int* in_sizes, int n_in,
                              void* d_out, int out_size) {
    const float* x  = (const float*)d_in[0];   // (8, 661500, 2) f32
    const float* fb = (const float*)d_in[1];   // (128, 1025)   f32
    float* out = (float*)d_out;                // (8, 128, 1292, 2) f32

    cudaFuncSetAttribute(fft_mel_kernel,
                         cudaFuncAttributeMaxDynamicSharedMemorySize, SMEM_BYTES);
    init_all<<<129, 256>>>(fb);
    fft_mel_kernel<<<dim3(T_FRAMES / 2, 8), 256, SMEM_BYTES>>>(x, out);
}

// round 10
// speedup vs baseline: 9.2001x; 1.0835x over previous
#include <cuda_runtime.h>
#include <cuda_bf16.h>

// ---------------- problem constants ----------------
#define S_LEN    661500
#define HOP      512
#define NFFT     2048
#define T_FRAMES 1292
#define N_BINS   1025
#define N_MELS   128
#define BW       64                // mel band width (max real ~54)
#define PWS      1056              // smem power row stride (>= 1025+31 guard)

// smem skews (index units: float2)
#define SKD(i) ((i) + ((i) >> 4))  // data arrays
#define SKT(i) ((i) + ((i) >> 3))  // twiddle table

#define A2  (SKD(2047) + 2)        // 2176 float2 per data array
#define TWN (SKT(511) + 2)         // 576 float2 twiddle table
#define SMEM_F2 (2 * A2 + TWN)     // 2 frames x 1 in-place array + twiddles
#define SMEM_BYTES (SMEM_F2 * 8)   // 39424

// ---------------- device statics ----------------
__device__ float  g_bandT[BW * N_MELS];   // [tap][mel] transposed, zero padded
__device__ int    g_lo[N_MELS];
__device__ int    g_nch[N_MELS];          // ceil(width/16), 1..4
__device__ float  g_win[NFFT];
__device__ float2 g_tw2048[1025];

// ---------------- init ----------------
__global__ void init_all(const float* __restrict__ fb) {
    const int tid = threadIdx.x;
    if (blockIdx.x == 128) {
        for (int i = tid; i < NFFT; i += 256)
            g_win[i] = 0.5f - 0.5f * cospif((float)i / 1024.0f);
        for (int i = tid; i < 1025; i += 256) {
            float s, c; sincospif(-(float)i / 1024.0f, &s, &c);
            g_tw2048[i] = make_float2(c, s);
        }
        return;
    }
    __shared__ int slo, shi;
    const int m = blockIdx.x;
    if (tid == 0) { slo = N_BINS; shi = -1; }
    __syncthreads();
    int l = N_BINS, h = -1;
    for (int k = tid; k < N_BINS; k += blockDim.x) {
        if (fb[m * N_BINS + k] != 0.0f) { l = min(l, k); h = max(h, k); }
    }
    atomicMin(&slo, l);
    atomicMax(&shi, h);
    __syncthreads();
    const int lo = (shi >= 0) ? slo : 0;
    for (int i = tid; i < BW; i += blockDim.x) {
        int k = lo + i;
        g_bandT[i * N_MELS + m] = (k <= shi && k < N_BINS) ? fb[m * N_BINS + k] : 0.0f;
    }
    if (tid == 0) {
        g_lo[m] = lo;
        int w = (shi >= lo) ? (shi - lo + 1) : 1;
        if (w > BW) w = BW;
        g_nch[m] = (w + 15) >> 4;
    }
}

// ---------------- complex helpers ----------------
__device__ __forceinline__ float2 cmul(float2 a, float2 b) {
    return make_float2(fmaf(a.x, b.x, -a.y * b.y), fmaf(a.x, b.y, a.y * b.x));
}
__device__ __forceinline__ float2 cadd(float2 a, float2 b) { return make_float2(a.x + b.x, a.y + b.y); }
__device__ __forceinline__ float2 csub(float2 a, float2 b) { return make_float2(a.x - b.x, a.y - b.y); }
__device__ __forceinline__ float2 cmulni(float2 a) { return make_float2(a.y, -a.x); }  // -i*a

// ---------------- radix-8 butterfly (DIT, natural order) ----------------
__device__ __forceinline__ void bfly8(float2* a) {
    const float C = 0.70710678118654752f;
    float2 s02 = cadd(a[0], a[4]), d02 = csub(a[0], a[4]);
    float2 s46 = cadd(a[2], a[6]), d46 = cmulni(csub(a[2], a[6]));
    float2 e0 = cadd(s02, s46), e2 = csub(s02, s46);
    float2 e1 = cadd(d02, d46), e3 = csub(d02, d46);
    float2 s13 = cadd(a[1], a[5]), d13 = csub(a[1], a[5]);
    float2 s57 = cadd(a[3], a[7]), d57 = cmulni(csub(a[3], a[7]));
    float2 o0 = cadd(s13, s57), o2 = csub(s13, s57);
    float2 o1 = cadd(d13, d57), o3 = csub(d13, d57);
    float2 t1 = make_float2(C * (o1.x + o1.y), C * (o1.y - o1.x));
    float2 t2 = cmulni(o2);
    float2 t3 = make_float2(C * (o3.y - o3.x), -C * (o3.x + o3.y));
    a[0] = cadd(e0, o0); a[4] = csub(e0, o0);
    a[1] = cadd(e1, t1); a[5] = csub(e1, t1);
    a[2] = cadd(e2, t2); a[6] = csub(e2, t2);
    a[3] = cadd(e3, t3); a[7] = csub(e3, t3);
}

// ---------------- radix-16 butterfly (4x4 Cooley-Tukey, natural order) ----------------
__device__ __forceinline__ void bfly16(float2* a) {
    const float C8 = 0.70710678118654752f;
    const float C1 = 0.92387953251128676f;   // cos(pi/8)
    const float S1 = 0.38268343236508977f;   // sin(pi/8)
    float2 B[4][4];
#pragma unroll
    for (int n2 = 0; n2 < 4; n2++) {
        float2 x0 = a[n2], x1 = a[n2 + 4], x2 = a[n2 + 8], x3 = a[n2 + 12];
        float2 t0 = cadd(x0, x2), t1 = csub(x0, x2);
        float2 t2 = cadd(x1, x3), t3 = cmulni(csub(x1, x3));
        B[n2][0] = cadd(t0, t2); B[n2][1] = cadd(t1, t3);
        B[n2][2] = csub(t0, t2); B[n2][3] = csub(t1, t3);
    }
    B[1][1] = cmul(B[1][1], make_float2(C1, -S1));
    B[1][2] = cmul(B[1][2], make_float2(C8, -C8));
    B[1][3] = cmul(B[1][3], make_float2(S1, -C1));
    B[2][1] = cmul(B[2][1], make_float2(C8, -C8));
    B[2][2] = cmulni(B[2][2]);
    B[2][3] = cmul(B[2][3], make_float2(-C8, -C8));
    B[3][1] = cmul(B[3][1], make_float2(S1, -C1));
    B[3][2] = cmul(B[3][2], make_float2(-C8, -C8));
    B[3][3] = cmul(B[3][3], make_float2(-C1, S1));
#pragma unroll
    for (int k1 = 0; k1 < 4; k1++) {
        float2 x0 = B[0][k1], x1 = B[1][k1], x2 = B[2][k1], x3 = B[3][k1];
        float2 t0 = cadd(x0, x2), t1 = csub(x0, x2);
        float2 t2 = cadd(x1, x3), t3 = cmulni(csub(x1, x3));
        a[k1]      = cadd(t0, t2);
        a[k1 + 4]  = cadd(t1, t3);
        a[k1 + 8]  = csub(t0, t2);
        a[k1 + 12] = csub(t1, t3);
    }
}

// ---------------- final radix-8 butterfly (L=256): Z[m] = Z[bf + 256m] ----------------
__device__ __forceinline__ void fft8_final(const float2* __restrict__ src,
                                           const float2* __restrict__ tws,
                                           int bf, float2* Z) {
#pragma unroll
    for (int k = 0; k < 8; k++) Z[k] = src[SKD(bf + 256 * k)];
    float2 w1 = tws[SKT(bf)];
    float2 wk = w1;
    Z[1] = cmul(Z[1], wk);
#pragma unroll
    for (int k = 2; k < 8; k++) { wk = cmul(wk, w1); Z[k] = cmul(Z[k], wk); }
    bfly8(Z);
}

// ---------------- fused: 2 frames/block, in-place radix-16/16/8 FFT + power + mel ----------------
__global__ __launch_bounds__(256, 4) void fft_mel_kernel(const float* __restrict__ x,
                                                         float* __restrict__ out) {
    extern __shared__ float2 smem[];
    float2* tws = smem + 2 * A2;

    const int j  = threadIdx.x;
    const int f  = j >> 7;             // frame within block (0/1)
    const int jj = j & 127;
    const int t  = blockIdx.x * 2 + f;
    const int b  = blockIdx.y;
    const float2* xp = (const float2*)x + (size_t)b * S_LEN;  // (ch0, ch1)

    float2* za = smem + f * A2;        // single in-place array per frame

    for (int i = j; i < 512; i += 256) tws[SKT(i)] = g_tw2048[i];

    // fused load + radix-16 stage 0 (L=1, unit twiddles): a_k = z[jj+128k] -> za[16jj+m]
    {
        const int base = t * HOP - 1024;
        float2 a[16];
#pragma unroll
        for (int k = 0; k < 16; k++) {
            int n = jj + 128 * k;
            int p = base + n;
            p = (p < 0) ? -p : ((p >= S_LEN) ? 2 * S_LEN - 2 - p : p);
            float2 v = __ldg(&xp[p]);
            float  w = g_win[n];
            a[k] = make_float2(w * v.x, w * v.y);   // z = win*(ch0 + i*ch1)
        }
        bfly16(a);
#pragma unroll
        for (int m = 0; m < 16; m++) za[SKD(16 * jj + m)] = a[m];
    }
    __syncthreads();

    // radix-16 stage 1 (L=16, STEP=8), IN-PLACE: read -> compute -> barrier -> write
    {
        const int p = jj & 15;
        float2 a[16];
#pragma unroll
        for (int k = 0; k < 16; k++) a[k] = za[SKD(jj + 128 * k)];
        float2 w1 = tws[SKT(p * 8)];
        float2 wk = w1;
        a[1] = cmul(a[1], wk);
#pragma unroll
        for (int k = 2; k < 16; k++) { wk = cmul(wk, w1); a[k] = cmul(a[k], wk); }
        bfly16(a);
        __syncthreads();                // all reads complete before in-place writes
        const int o = ((jj >> 4) << 8) | p;
#pragma unroll
        for (int m = 0; m < 16; m++) za[SKD(o + 16 * m)] = a[m];
    }
    __syncthreads();

    // fused final radix-8 (L=256) + two-real unpack + power -> pw (aliases za, in-place)
    float* pw = (float*)za;
    {
        const int bf0 = jj;
        const int bf1 = (jj == 0) ? 128 : 256 - jj;
        float2 ZA[8], ZB[8];
        fft8_final(za, tws, bf0, ZA);   // ZA[m] = Z[bf0 + 256m]
        fft8_final(za, tws, bf1, ZB);   // ZB[m] = Z[bf1 + 256m]
        __syncthreads();                // all reads complete before pw overwrites za

#define PWR(K, ZK, ZN)                                                  \
        {                                                               \
            float sr = (ZK).x + (ZN).x, si = (ZK).y - (ZN).y;           \
            float dr = (ZK).x - (ZN).x, di = (ZK).y + (ZN).y;           \
            pw[(K)]       = 0.25f * (sr * sr + si * si);                \
            pw[PWS + (K)] = 0.25f * (di * di + dr * dr);                \
        }
        if (jj == 0) {
            PWR(0,    ZA[0], ZA[0]);
            PWR(256,  ZA[1], ZA[7]);
            PWR(512,  ZA[2], ZA[6]);
            PWR(768,  ZA[3], ZA[5]);
            PWR(1024, ZA[4], ZA[4]);
#pragma unroll
            for (int m = 0; m < 4; m++) PWR(128 + 256 * m, ZB[m], ZB[7 - m]);
        } else {
#pragma unroll
            for (int m = 0; m < 4; m++) {
                PWR(jj + 256 * m,         ZA[m], ZB[7 - m]);   // Z[k], Z[2048-k]
                PWR((256 - jj) + 256 * m, ZB[m], ZA[7 - m]);
            }
        }
#undef PWR
    }
    if (jj < (PWS - N_BINS)) {          // zero NaN-guard tail (bins 1025..1055)
        pw[N_BINS + jj]       = 0.0f;
        pw[PWS + N_BINS + jj] = 0.0f;
    }
    __syncthreads();

    // banded mel: thread j -> mel m = j&127, channel ch = j>>7, BOTH frames
    const int ch = j >> 7;
    const int m  = j & 127;
    const int lo = g_lo[m];
    const float* p0 = (const float*)(smem)      + ch * PWS + lo;   // frame 0 power
    const float* p1 = (const float*)(smem + A2) + ch * PWS + lo;   // frame 1 power
    const float* bt = g_bandT + m;      // column m, row stride 128 (coalesced)
    const int umax = __reduce_max_sync(0xffffffffu, g_nch[m]);
    float q0 = 0.0f, q1 = 0.0f, q2 = 0.0f, q3 = 0.0f;   // frame 0
    float r0 = 0.0f, r1 = 0.0f, r2 = 0.0f, r3 = 0.0f;   // frame 1

#define MEL_DOT(TAPS)                                                   \
    _Pragma("unroll")                                                   \
    for (int i = 0; i < (TAPS); i += 4) {                               \
        float b0 = bt[(i)     * N_MELS];                                \
        float b1 = bt[(i + 1) * N_MELS];                                \
        float b2 = bt[(i + 2) * N_MELS];                                \
        float b3 = bt[(i + 3) * N_MELS];                                \
        q0 = fmaf(b0, p0[i],     q0);  r0 = fmaf(b0, p1[i],     r0);    \
        q1 = fmaf(b1, p0[i + 1], q1);  r1 = fmaf(b1, p1[i + 1], r1);    \
        q2 = fmaf(b2, p0[i + 2], q2);  r2 = fmaf(b2, p1[i + 2], r2);    \
        q3 = fmaf(b3, p0[i + 3], q3);  r3 = fmaf(b3, p1[i + 3], r3);    \
    }

    switch (umax) {
        case 1: MEL_DOT(16); break;
        case 2: MEL_DOT(32); break;
        case 3: MEL_DOT(48); break;
        default: MEL_DOT(64); break;
    }
#undef MEL_DOT

    const size_t obase = (((size_t)b * N_MELS + m) * T_FRAMES + blockIdx.x * 2) * 2 + ch;
    out[obase]     = (q0 + q1) + (q2 + q3);
    out[obase + 2] = (r0 + r1) + (r2 + r3);
}

// ---------------- entry point ----------------
extern "C" void kernel_launch(void* const* d_in, const int* in_sizes, int n_in,
                              void* d_out, int out_size) {
    const float* x  = (const float*)d_in[0];   // (8, 661500, 2) f32
    const float* fb = (const float*)d_in[1];   // (128, 1025)   f32
    float* out = (float*)d_out;                // (8, 128, 1292, 2) f32

    cudaFuncSetAttribute(fft_mel_kernel,
                         cudaFuncAttributeMaxDynamicSharedMemorySize, SMEM_BYTES);
    init_all<<<129, 256>>>(fb);
    fft_mel_kernel<<<dim3(T_FRAMES / 2, 8), 256, SMEM_BYTES>>>(x, out);
}

// round 11
// speedup vs baseline: 9.2663x; 1.0072x over previous
#include <cuda_runtime.h>
#include <cuda_bf16.h>

// ---------------- problem constants ----------------
#define S_LEN    661500
#define HOP      512
#define NFFT     2048
#define T_FRAMES 1292
#define N_BINS   1025
#define N_MELS   128
#define BW       96                // aligned mel band window (max real ~85)
#define PWS      1088              // smem power row stride (34*32; >= 971+96)

// smem skews (index units: float2)
#define SKD(i) ((i) + ((i) >> 4))  // data arrays
#define SKT(i) ((i) + ((i) >> 3))  // twiddle table

#define A2  (SKD(2047) + 2)        // 2176 float2 per data array (4352 floats, %32==0)
#define TWN (SKT(511) + 2)         // 576 float2 twiddle table
#define SMEM_F2 (2 * A2 + TWN)     // 2 frames x 1 in-place array + twiddles
#define SMEM_BYTES (SMEM_F2 * 8)   // 39424

// ---------------- device statics ----------------
__device__ float  g_bandT[BW * N_MELS];   // [tap][mel], taps relative to align[m]
__device__ int    g_lo[N_MELS];           // align[m]  (== m mod 32)
__device__ int    g_nch[N_MELS];          // ceil(width'/16), 1..6
__device__ float  g_win[NFFT];
__device__ float2 g_tw2048[1025];

// ---------------- init ----------------
__global__ void init_all(const float* __restrict__ fb) {
    const int tid = threadIdx.x;
    if (blockIdx.x == 128) {
        for (int i = tid; i < NFFT; i += 256)
            g_win[i] = 0.5f - 0.5f * cospif((float)i / 1024.0f);
        for (int i = tid; i < 1025; i += 256) {
            float s, c; sincospif(-(float)i / 1024.0f, &s, &c);
            g_tw2048[i] = make_float2(c, s);
        }
        return;
    }
    __shared__ int slo, shi;
    const int m = blockIdx.x;
    if (tid == 0) { slo = N_BINS; shi = -1; }
    __syncthreads();
    int l = N_BINS, h = -1;
    for (int k = tid; k < N_BINS; k += blockDim.x) {
        if (fb[m * N_BINS + k] != 0.0f) { l = min(l, k); h = max(h, k); }
    }
    atomicMin(&slo, l);
    atomicMax(&shi, h);
    __syncthreads();
    const int lo = (shi >= 0) ? slo : 0;
    const int hi = (shi >= 0) ? shi : 0;
    // bank-aligned window start: align ≡ m (mod 32), align <= lo, align >= 0
    int align = lo - ((lo - m) & 31);
    if (align < 0) align = 0;           // unreachable for slaney fb; safety
    for (int i = tid; i < BW; i += blockDim.x) {
        int k = align + i;
        g_bandT[i * N_MELS + m] = (k >= lo && k <= hi && k < N_BINS) ? fb[m * N_BINS + k] : 0.0f;
    }
    if (tid == 0) {
        g_lo[m] = align;
        int w = hi - align + 1;
        if (w < 1) w = 1;
        if (w > BW) w = BW;
        g_nch[m] = (w + 15) >> 4;       // 1..6
    }
}

// ---------------- complex helpers ----------------
__device__ __forceinline__ float2 cmul(float2 a, float2 b) {
    return make_float2(fmaf(a.x, b.x, -a.y * b.y), fmaf(a.x, b.y, a.y * b.x));
}
__device__ __forceinline__ float2 cadd(float2 a, float2 b) { return make_float2(a.x + b.x, a.y + b.y); }
__device__ __forceinline__ float2 csub(float2 a, float2 b) { return make_float2(a.x - b.x, a.y - b.y); }
__device__ __forceinline__ float2 cmulni(float2 a) { return make_float2(a.y, -a.x); }  // -i*a

// ---------------- radix-8 butterfly (DIT, natural order) ----------------
__device__ __forceinline__ void bfly8(float2* a) {
    const float C = 0.70710678118654752f;
    float2 s02 = cadd(a[0], a[4]), d02 = csub(a[0], a[4]);
    float2 s46 = cadd(a[2], a[6]), d46 = cmulni(csub(a[2], a[6]));
    float2 e0 = cadd(s02, s46), e2 = csub(s02, s46);
    float2 e1 = cadd(d02, d46), e3 = csub(d02, d46);
    float2 s13 = cadd(a[1], a[5]), d13 = csub(a[1], a[5]);
    float2 s57 = cadd(a[3], a[7]), d57 = cmulni(csub(a[3], a[7]));
    float2 o0 = cadd(s13, s57), o2 = csub(s13, s57);
    float2 o1 = cadd(d13, d57), o3 = csub(d13, d57);
    float2 t1 = make_float2(C * (o1.x + o1.y), C * (o1.y - o1.x));
    float2 t2 = cmulni(o2);
    float2 t3 = make_float2(C * (o3.y - o3.x), -C * (o3.x + o3.y));
    a[0] = cadd(e0, o0); a[4] = csub(e0, o0);
    a[1] = cadd(e1, t1); a[5] = csub(e1, t1);
    a[2] = cadd(e2, t2); a[6] = csub(e2, t2);
    a[3] = cadd(e3, t3); a[7] = csub(e3, t3);
}

// ---------------- radix-16 butterfly (4x4 Cooley-Tukey, natural order) ----------------
__device__ __forceinline__ void bfly16(float2* a) {
    const float C8 = 0.70710678118654752f;
    const float C1 = 0.92387953251128676f;   // cos(pi/8)
    const float S1 = 0.38268343236508977f;   // sin(pi/8)
    float2 B[4][4];
#pragma unroll
    for (int n2 = 0; n2 < 4; n2++) {
        float2 x0 = a[n2], x1 = a[n2 + 4], x2 = a[n2 + 8], x3 = a[n2 + 12];
        float2 t0 = cadd(x0, x2), t1 = csub(x0, x2);
        float2 t2 = cadd(x1, x3), t3 = cmulni(csub(x1, x3));
        B[n2][0] = cadd(t0, t2); B[n2][1] = cadd(t1, t3);
        B[n2][2] = csub(t0, t2); B[n2][3] = csub(t1, t3);
    }
    B[1][1] = cmul(B[1][1], make_float2(C1, -S1));
    B[1][2] = cmul(B[1][2], make_float2(C8, -C8));
    B[1][3] = cmul(B[1][3], make_float2(S1, -C1));
    B[2][1] = cmul(B[2][1], make_float2(C8, -C8));
    B[2][2] = cmulni(B[2][2]);
    B[2][3] = cmul(B[2][3], make_float2(-C8, -C8));
    B[3][1] = cmul(B[3][1], make_float2(S1, -C1));
    B[3][2] = cmul(B[3][2], make_float2(-C8, -C8));
    B[3][3] = cmul(B[3][3], make_float2(-C1, S1));
#pragma unroll
    for (int k1 = 0; k1 < 4; k1++) {
        float2 x0 = B[0][k1], x1 = B[1][k1], x2 = B[2][k1], x3 = B[3][k1];
        float2 t0 = cadd(x0, x2), t1 = csub(x0, x2);
        float2 t2 = cadd(x1, x3), t3 = cmulni(csub(x1, x3));
        a[k1]      = cadd(t0, t2);
        a[k1 + 4]  = cadd(t1, t3);
        a[k1 + 8]  = csub(t0, t2);
        a[k1 + 12] = csub(t1, t3);
    }
}

// ---------------- final radix-8 butterfly (L=256): Z[m] = Z[bf + 256m] ----------------
__device__ __forceinline__ void fft8_final(const float2* __restrict__ src,
                                           const float2* __restrict__ tws,
                                           int bf, float2* Z) {
#pragma unroll
    for (int k = 0; k < 8; k++) Z[k] = src[SKD(bf + 256 * k)];
    float2 w1 = tws[SKT(bf)];
    float2 wk = w1;
    Z[1] = cmul(Z[1], wk);
#pragma unroll
    for (int k = 2; k < 8; k++) { wk = cmul(wk, w1); Z[k] = cmul(Z[k], wk); }
    bfly8(Z);
}

// ---------------- fused: 2 frames/block, in-place radix-16/16/8 FFT + power + mel ----------------
__global__ __launch_bounds__(256, 4) void fft_mel_kernel(const float* __restrict__ x,
                                                         float* __restrict__ out) {
    extern __shared__ float2 smem[];
    float2* tws = smem + 2 * A2;

    const int j  = threadIdx.x;
    const int f  = j >> 7;             // frame within block (0/1)
    const int jj = j & 127;
    const int t  = blockIdx.x * 2 + f;
    const int b  = blockIdx.y;
    const float2* xp = (const float2*)x + (size_t)b * S_LEN;  // (ch0, ch1)

    float2* za = smem + f * A2;        // single in-place array per frame

    for (int i = j; i < 512; i += 256) tws[SKT(i)] = g_tw2048[i];

    // fused load + radix-16 stage 0 (L=1, unit twiddles): a_k = z[jj+128k] -> za[16jj+m]
    {
        const int base = t * HOP - 1024;
        float2 a[16];
#pragma unroll
        for (int k = 0; k < 16; k++) {
            int n = jj + 128 * k;
            int p = base + n;
            p = (p < 0) ? -p : ((p >= S_LEN) ? 2 * S_LEN - 2 - p : p);
            float2 v = __ldg(&xp[p]);
            float  w = g_win[n];
            a[k] = make_float2(w * v.x, w * v.y);   // z = win*(ch0 + i*ch1)
        }
        bfly16(a);
#pragma unroll
        for (int m = 0; m < 16; m++) za[SKD(16 * jj + m)] = a[m];
    }
    __syncthreads();

    // radix-16 stage 1 (L=16, STEP=8), IN-PLACE
    {
        const int p = jj & 15;
        float2 a[16];
#pragma unroll
        for (int k = 0; k < 16; k++) a[k] = za[SKD(jj + 128 * k)];
        float2 w1 = tws[SKT(p * 8)];
        float2 wk = w1;
        a[1] = cmul(a[1], wk);
#pragma unroll
        for (int k = 2; k < 16; k++) { wk = cmul(wk, w1); a[k] = cmul(a[k], wk); }
        bfly16(a);
        __syncthreads();                // all reads complete before in-place writes
        const int o = ((jj >> 4) << 8) | p;
#pragma unroll
        for (int m = 0; m < 16; m++) za[SKD(o + 16 * m)] = a[m];
    }
    __syncthreads();

    // fused final radix-8 (L=256) + two-real unpack + power -> pw (aliases za)
    float* pw = (float*)za;
    {
        const int bf0 = jj;
        const int bf1 = (jj == 0) ? 128 : 256 - jj;
        float2 ZA[8], ZB[8];
        fft8_final(za, tws, bf0, ZA);   // ZA[m] = Z[bf0 + 256m]
        fft8_final(za, tws, bf1, ZB);   // ZB[m] = Z[bf1 + 256m]
        __syncthreads();                // all reads complete before pw overwrites za

#define PWR(K, ZK, ZN)                                                  \
        {                                                               \
            float sr = (ZK).x + (ZN).x, si = (ZK).y - (ZN).y;           \
            float dr = (ZK).x - (ZN).x, di = (ZK).y + (ZN).y;           \
            pw[(K)]       = 0.25f * (sr * sr + si * si);                \
            pw[PWS + (K)] = 0.25f * (di * di + dr * dr);                \
        }
        if (jj == 0) {
            PWR(0,    ZA[0], ZA[0]);
            PWR(256,  ZA[1], ZA[7]);
            PWR(512,  ZA[2], ZA[6]);
            PWR(768,  ZA[3], ZA[5]);
            PWR(1024, ZA[4], ZA[4]);
#pragma unroll
            for (int m = 0; m < 4; m++) PWR(128 + 256 * m, ZB[m], ZB[7 - m]);
        } else {
#pragma unroll
            for (int m = 0; m < 4; m++) {
                PWR(jj + 256 * m,         ZA[m], ZB[7 - m]);   // Z[k], Z[2048-k]
                PWR((256 - jj) + 256 * m, ZB[m], ZA[7 - m]);
            }
        }
#undef PWR
    }
    // zero guard tail (bins 1025..1087) so aligned-window over-reads hit zeros
#pragma unroll
    for (int i = jj; i < (PWS - N_BINS); i += 128) {
        pw[N_BINS + i]       = 0.0f;
        pw[PWS + N_BINS + i] = 0.0f;
    }
    __syncthreads();

    // banded mel: thread j -> mel m = j&127, channel ch = j>>7, BOTH frames.
    // align[m] ≡ m (mod 32)  ⇒  at each unrolled step the 32 lanes of a warp
    // read 32 distinct banks: conflict-free LDS. bandT reads stay coalesced.
    const int ch = j >> 7;
    const int m  = j & 127;
    const int lo = g_lo[m];             // aligned window start
    const float* p0 = (const float*)(smem)      + ch * PWS + lo;   // frame 0
    const float* p1 = (const float*)(smem + A2) + ch * PWS + lo;   // frame 1
    const float* bt = g_bandT + m;      // column m, row stride 128 (coalesced)
    const int umax = __reduce_max_sync(0xffffffffu, g_nch[m]);
    float q0 = 0.0f, q1 = 0.0f, q2 = 0.0f, q3 = 0.0f;   // frame 0
    float r0 = 0.0f, r1 = 0.0f, r2 = 0.0f, r3 = 0.0f;   // frame 1

#define MEL_DOT(TAPS)                                                   \
    _Pragma("unroll")                                                   \
    for (int i = 0; i < (TAPS); i += 4) {                               \
        float b0 = bt[(i)     * N_MELS];                                \
        float b1 = bt[(i + 1) * N_MELS];                                \
        float b2 = bt[(i + 2) * N_MELS];                                \
        float b3 = bt[(i + 3) * N_MELS];                                \
        q0 = fmaf(b0, p0[i],     q0);  r0 = fmaf(b0, p1[i],     r0);    \
        q1 = fmaf(b1, p0[i + 1], q1);  r1 = fmaf(b1, p1[i + 1], r1);    \
        q2 = fmaf(b2, p0[i + 2], q2);  r2 = fmaf(b2, p1[i + 2], r2);    \
        q3 = fmaf(b3, p0[i + 3], q3);  r3 = fmaf(b3, p1[i + 3], r3);    \
    }

    switch (umax) {
        case 1: MEL_DOT(16); break;
        case 2: MEL_DOT(32); break;
        case 3: MEL_DOT(48); break;
        case 4: MEL_DOT(64); break;
        case 5: MEL_DOT(80); break;
        default: MEL_DOT(96); break;
    }
#undef MEL_DOT

    const size_t obase = (((size_t)b * N_MELS + m) * T_FRAMES + blockIdx.x * 2) * 2 + ch;
    out[obase]     = (q0 + q1) + (q2 + q3);
    out[obase + 2] = (r0 + r1) + (r2 + r3);
}

// ---------------- entry point ----------------
extern "C" void kernel_launch(void* const* d_in, const int* in_sizes, int n_in,
                              void* d_out, int out_size) {
    const float* x  = (const float*)d_in[0];   // (8, 661500, 2) f32
    const float* fb = (const float*)d_in[1];   // (128, 1025)   f32
    float* out = (float*)d_out;                // (8, 128, 1292, 2) f32

    cudaFuncSetAttribute(fft_mel_kernel,
                         cudaFuncAttributeMaxDynamicSharedMemorySize, SMEM_BYTES);
    init_all<<<129, 256>>>(fb);
    fft_mel_kernel<<<dim3(T_FRAMES / 2, 8), 256, SMEM_BYTES>>>(x, out);
}

// round 12
// speedup vs baseline: 9.2909x; 1.0027x over previous
#include <cuda_runtime.h>
#include <cuda_bf16.h>

// ---------------- problem constants ----------------
#define S_LEN    661500
#define HOP      512
#define NFFT     2048
#define T_FRAMES 1292
#define N_BINS   1025
#define N_MELS   128
#define BW       96                // mel band window cap (max real ~54 + ext <32)
#define PWS      1088              // power row stride (34*32)
#define PWBASE   32                // pw starts 32 floats into the buffer (neg-align guard)

// smem skews (index units: float2)
#define SKD(i) ((i) + ((i) >> 4))  // data arrays
#define SKT(i) ((i) + ((i) >> 3))  // twiddle table

#define A2  (SKD(2047) + 2)        // 2176 float2 per data array (4352 floats)
#define TWN (SKT(511) + 2)         // 576 float2 twiddle table
#define SMEM_F2 (2 * A2 + TWN)     // 2 frames x 1 in-place array + twiddles
#define SMEM_BYTES (SMEM_F2 * 8)   // 39424

// ---------------- device statics ----------------
__device__ float  g_bandT[BW * N_MELS];   // [tap][mel], taps relative to align[m]
__device__ int    g_lo[N_MELS];           // align[m] (bank-permuted, may be <0)
__device__ int    g_nch[N_MELS];          // ceil(width'/16), 1..6
__device__ int    g_rawlo[N_MELS], g_rawhi[N_MELS];
__device__ float  g_win[NFFT];
__device__ float2 g_tw2048[1025];

// ---------------- init pass 1: band extents + window + twiddles ----------------
__global__ void init_scan(const float* __restrict__ fb) {
    const int tid = threadIdx.x;
    if (blockIdx.x == 128) {
        for (int i = tid; i < NFFT; i += 256)
            g_win[i] = 0.5f - 0.5f * cospif((float)i / 1024.0f);
        for (int i = tid; i < 1025; i += 256) {
            float s, c; sincospif(-(float)i / 1024.0f, &s, &c);
            g_tw2048[i] = make_float2(c, s);
        }
        return;
    }
    __shared__ int slo, shi;
    const int m = blockIdx.x;
    if (tid == 0) { slo = N_BINS; shi = -1; }
    __syncthreads();
    int l = N_BINS, h = -1;
    for (int k = tid; k < N_BINS; k += blockDim.x) {
        if (fb[m * N_BINS + k] != 0.0f) { l = min(l, k); h = max(h, k); }
    }
    atomicMin(&slo, l);
    atomicMax(&shi, h);
    __syncthreads();
    if (tid == 0) {
        g_rawlo[m] = (shi >= 0) ? slo : 0;
        g_rawhi[m] = (shi >= 0) ? shi : 0;
    }
}

// ---------------- init pass 2: per-warp optimal bank permutation + band fill ----------------
__global__ void init_perm(const float* __restrict__ fb) {
    const int m    = threadIdx.x;        // 128 threads, warp w owns mels 32w..32w+31
    const int lane = m & 31;
    const int lo = g_rawlo[m];
    const int hi = g_rawhi[m];
    const int width = hi - lo + 1;
    const int key = lo & 31;

    // rank of this lane's key within the warp (stable, tie-break by lane)
    int rank = 0;
#pragma unroll
    for (int l = 0; l < 32; l++) {
        int ok = __shfl_sync(0xffffffffu, key, l);
        rank += (ok < key) || (ok == key && l < lane);
    }
    // choose cyclic shift s minimizing warp-max(width + extension), tie: min sum
    int best_s = 0, best_max = 1 << 30, best_sum = 1 << 30;
    for (int s = 0; s < 32; s++) {
        int tgt = (rank + s) & 31;
        int ext = (key - tgt) & 31;
        int val = width + ext;
        int vmax = __reduce_max_sync(0xffffffffu, val);
        int vsum = __reduce_add_sync(0xffffffffu, val);
        if (vmax < best_max || (vmax == best_max && vsum < best_sum)) {
            best_max = vmax; best_sum = vsum; best_s = s;
        }
    }
    const int tgt = (rank + best_s) & 31;
    const int align = lo - ((lo - tgt) & 31);   // align ≡ tgt (mod 32), may be < 0 (≥ -31)
    g_lo[m] = align;
    int wp = hi - align + 1;
    if (wp < 1) wp = 1;
    if (wp > BW) wp = BW;
    g_nch[m] = (wp + 15) >> 4;                  // 1..6

    for (int i = 0; i < BW; i++) {
        int k = align + i;
        g_bandT[i * N_MELS + m] =
            (k >= lo && k <= hi && k < N_BINS) ? fb[m * N_BINS + k] : 0.0f;
    }
}

// ---------------- complex helpers ----------------
__device__ __forceinline__ float2 cmul(float2 a, float2 b) {
    return make_float2(fmaf(a.x, b.x, -a.y * b.y), fmaf(a.x, b.y, a.y * b.x));
}
__device__ __forceinline__ float2 cadd(float2 a, float2 b) { return make_float2(a.x + b.x, a.y + b.y); }
__device__ __forceinline__ float2 csub(float2 a, float2 b) { return make_float2(a.x - b.x, a.y - b.y); }
__device__ __forceinline__ float2 cmulni(float2 a) { return make_float2(a.y, -a.x); }  // -i*a

// ---------------- radix-8 butterfly (DIT, natural order) ----------------
__device__ __forceinline__ void bfly8(float2* a) {
    const float C = 0.70710678118654752f;
    float2 s02 = cadd(a[0], a[4]), d02 = csub(a[0], a[4]);
    float2 s46 = cadd(a[2], a[6]), d46 = cmulni(csub(a[2], a[6]));
    float2 e0 = cadd(s02, s46), e2 = csub(s02, s46);
    float2 e1 = cadd(d02, d46), e3 = csub(d02, d46);
    float2 s13 = cadd(a[1], a[5]), d13 = csub(a[1], a[5]);
    float2 s57 = cadd(a[3], a[7]), d57 = cmulni(csub(a[3], a[7]));
    float2 o0 = cadd(s13, s57), o2 = csub(s13, s57);
    float2 o1 = cadd(d13, d57), o3 = csub(d13, d57);
    float2 t1 = make_float2(C * (o1.x + o1.y), C * (o1.y - o1.x));
    float2 t2 = cmulni(o2);
    float2 t3 = make_float2(C * (o3.y - o3.x), -C * (o3.x + o3.y));
    a[0] = cadd(e0, o0); a[4] = csub(e0, o0);
    a[1] = cadd(e1, t1); a[5] = csub(e1, t1);
    a[2] = cadd(e2, t2); a[6] = csub(e2, t2);
    a[3] = cadd(e3, t3); a[7] = csub(e3, t3);
}

// ---------------- radix-16 butterfly (4x4 Cooley-Tukey, natural order) ----------------
__device__ __forceinline__ void bfly16(float2* a) {
    const float C8 = 0.70710678118654752f;
    const float C1 = 0.92387953251128676f;   // cos(pi/8)
    const float S1 = 0.38268343236508977f;   // sin(pi/8)
    float2 B[4][4];
#pragma unroll
    for (int n2 = 0; n2 < 4; n2++) {
        float2 x0 = a[n2], x1 = a[n2 + 4], x2 = a[n2 + 8], x3 = a[n2 + 12];
        float2 t0 = cadd(x0, x2), t1 = csub(x0, x2);
        float2 t2 = cadd(x1, x3), t3 = cmulni(csub(x1, x3));
        B[n2][0] = cadd(t0, t2); B[n2][1] = cadd(t1, t3);
        B[n2][2] = csub(t0, t2); B[n2][3] = csub(t1, t3);
    }
    B[1][1] = cmul(B[1][1], make_float2(C1, -S1));
    B[1][2] = cmul(B[1][2], make_float2(C8, -C8));
    B[1][3] = cmul(B[1][3], make_float2(S1, -C1));
    B[2][1] = cmul(B[2][1], make_float2(C8, -C8));
    B[2][2] = cmulni(B[2][2]);
    B[2][3] = cmul(B[2][3], make_float2(-C8, -C8));
    B[3][1] = cmul(B[3][1], make_float2(S1, -C1));
    B[3][2] = cmul(B[3][2], make_float2(-C8, -C8));
    B[3][3] = cmul(B[3][3], make_float2(-C1, S1));
#pragma unroll
    for (int k1 = 0; k1 < 4; k1++) {
        float2 x0 = B[0][k1], x1 = B[1][k1], x2 = B[2][k1], x3 = B[3][k1];
        float2 t0 = cadd(x0, x2), t1 = csub(x0, x2);
        float2 t2 = cadd(x1, x3), t3 = cmulni(csub(x1, x3));
        a[k1]      = cadd(t0, t2);
        a[k1 + 4]  = cadd(t1, t3);
        a[k1 + 8]  = csub(t0, t2);
        a[k1 + 12] = csub(t1, t3);
    }
}

// ---------------- final radix-8 butterfly (L=256): Z[m] = Z[bf + 256m] ----------------
__device__ __forceinline__ void fft8_final(const float2* __restrict__ src,
                                           const float2* __restrict__ tws,
                                           int bf, float2* Z) {
#pragma unroll
    for (int k = 0; k < 8; k++) Z[k] = src[SKD(bf + 256 * k)];
    float2 w1 = tws[SKT(bf)];
    float2 wk = w1;
    Z[1] = cmul(Z[1], wk);
#pragma unroll
    for (int k = 2; k < 8; k++) { wk = cmul(wk, w1); Z[k] = cmul(Z[k], wk); }
    bfly8(Z);
}

// ---------------- fused: 2 frames/block, in-place radix-16/16/8 FFT + power + mel ----------------
__global__ __launch_bounds__(256, 4) void fft_mel_kernel(const float* __restrict__ x,
                                                         float* __restrict__ out) {
    extern __shared__ float2 smem[];
    float2* tws = smem + 2 * A2;

    const int j  = threadIdx.x;
    const int f  = j >> 7;             // frame within block (0/1)
    const int jj = j & 127;
    const int t  = blockIdx.x * 2 + f;
    const int b  = blockIdx.y;
    const float2* xp = (const float2*)x + (size_t)b * S_LEN;  // (ch0, ch1)

    float2* za = smem + f * A2;        // single in-place array per frame

    for (int i = j; i < 512; i += 256) tws[SKT(i)] = g_tw2048[i];

    // fused load + radix-16 stage 0 (L=1, unit twiddles): a_k = z[jj+128k] -> za[16jj+m]
    {
        const int base = t * HOP - 1024;
        float2 a[16];
#pragma unroll
        for (int k = 0; k < 16; k++) {
            int n = jj + 128 * k;
            int p = base + n;
            p = (p < 0) ? -p : ((p >= S_LEN) ? 2 * S_LEN - 2 - p : p);
            float2 v = __ldg(&xp[p]);
            float  w = g_win[n];
            a[k] = make_float2(w * v.x, w * v.y);   // z = win*(ch0 + i*ch1)
        }
        bfly16(a);
#pragma unroll
        for (int m = 0; m < 16; m++) za[SKD(16 * jj + m)] = a[m];
    }
    __syncthreads();

    // radix-16 stage 1 (L=16, STEP=8), IN-PLACE
    {
        const int p = jj & 15;
        float2 a[16];
#pragma unroll
        for (int k = 0; k < 16; k++) a[k] = za[SKD(jj + 128 * k)];
        float2 w1 = tws[SKT(p * 8)];
        float2 wk = w1;
        a[1] = cmul(a[1], wk);
#pragma unroll
        for (int k = 2; k < 16; k++) { wk = cmul(wk, w1); a[k] = cmul(a[k], wk); }
        bfly16(a);
        __syncthreads();                // all reads complete before in-place writes
        const int o = ((jj >> 4) << 8) | p;
#pragma unroll
        for (int m = 0; m < 16; m++) za[SKD(o + 16 * m)] = a[m];
    }
    __syncthreads();

    // fused final radix-8 (L=256) + two-real unpack + power -> pw (aliases za)
    float* pw = (float*)za + PWBASE;    // 32-float negative-align guard precedes pw
    {
        const int bf0 = jj;
        const int bf1 = (jj == 0) ? 128 : 256 - jj;
        float2 ZA[8], ZB[8];
        fft8_final(za, tws, bf0, ZA);   // ZA[m] = Z[bf0 + 256m]
        fft8_final(za, tws, bf1, ZB);   // ZB[m] = Z[bf1 + 256m]
        __syncthreads();                // all reads complete before pw overwrites za

#define PWR(K, ZK, ZN)                                                  \
        {                                                               \
            float sr = (ZK).x + (ZN).x, si = (ZK).y - (ZN).y;           \
            float dr = (ZK).x - (ZN).x, di = (ZK).y + (ZN).y;           \
            pw[(K)]       = 0.25f * (sr * sr + si * si);                \
            pw[PWS + (K)] = 0.25f * (di * di + dr * dr);                \
        }
        if (jj == 0) {
            PWR(0,    ZA[0], ZA[0]);
            PWR(256,  ZA[1], ZA[7]);
            PWR(512,  ZA[2], ZA[6]);
            PWR(768,  ZA[3], ZA[5]);
            PWR(1024, ZA[4], ZA[4]);
#pragma unroll
            for (int m = 0; m < 4; m++) PWR(128 + 256 * m, ZB[m], ZB[7 - m]);
        } else {
#pragma unroll
            for (int m = 0; m < 4; m++) {
                PWR(jj + 256 * m,         ZA[m], ZB[7 - m]);   // Z[k], Z[2048-k]
                PWR((256 - jj) + 256 * m, ZB[m], ZA[7 - m]);
            }
        }
#undef PWR
    }
    // zero guards: leading 32 floats (negative aligns) + tails of both channels
    if (jj < PWBASE) ((float*)za)[jj] = 0.0f;
#pragma unroll
    for (int i = jj; i < (PWS - N_BINS); i += 128) {
        pw[N_BINS + i]       = 0.0f;
        pw[PWS + N_BINS + i] = 0.0f;
    }
    __syncthreads();

    // banded mel: thread j -> mel m = j&127, channel ch = j>>7, BOTH frames.
    // align[m] mod 32 is a per-warp permutation ⇒ conflict-free LDS at each step.
    const int ch = j >> 7;
    const int m  = j & 127;
    const int lo = g_lo[m];             // permuted-aligned window start (may be <0)
    const float* p0 = (const float*)(smem)      + PWBASE + ch * PWS + lo;   // frame 0
    const float* p1 = (const float*)(smem + A2) + PWBASE + ch * PWS + lo;   // frame 1
    const float* bt = g_bandT + m;      // column m, row stride 128 (coalesced)
    const int umax = __reduce_max_sync(0xffffffffu, g_nch[m]);
    float q0 = 0.0f, q1 = 0.0f, q2 = 0.0f, q3 = 0.0f;   // frame 0
    float r0 = 0.0f, r1 = 0.0f, r2 = 0.0f, r3 = 0.0f;   // frame 1

#define MEL_DOT(TAPS)                                                   \
    _Pragma("unroll")                                                   \
    for (int i = 0; i < (TAPS); i += 4) {                               \
        float b0 = bt[(i)     * N_MELS];                                \
        float b1 = bt[(i + 1) * N_MELS];                                \
        float b2 = bt[(i + 2) * N_MELS];                                \
        float b3 = bt[(i + 3) * N_MELS];                                \
        q0 = fmaf(b0, p0[i],     q0);  r0 = fmaf(b0, p1[i],     r0);    \
        q1 = fmaf(b1, p0[i + 1], q1);  r1 = fmaf(b1, p1[i + 1], r1);    \
        q2 = fmaf(b2, p0[i + 2], q2);  r2 = fmaf(b2, p1[i + 2], r2);    \
        q3 = fmaf(b3, p0[i + 3], q3);  r3 = fmaf(b3, p1[i + 3], r3);    \
    }

    switch (umax) {
        case 1: MEL_DOT(16); break;
        case 2: MEL_DOT(32); break;
        case 3: MEL_DOT(48); break;
        case 4: MEL_DOT(64); break;
        case 5: MEL_DOT(80); break;
        default: MEL_DOT(96); break;
    }
#undef MEL_DOT

    const size_t obase = (((size_t)b * N_MELS + m) * T_FRAMES + blockIdx.x * 2) * 2 + ch;
    out[obase]     = (q0 + q1) + (q2 + q3);
    out[obase + 2] = (r0 + r1) + (r2 + r3);
}

// ---------------- entry point ----------------
extern "C" void kernel_launch(void* const* d_in, const int* in_sizes, int n_in,
                              void* d_out, int out_size) {
    const float* x  = (const float*)d_in[0];   // (8, 661500, 2) f32
    const float* fb = (const float*)d_in[1];   // (128, 1025)   f32
    float* out = (float*)d_out;                // (8, 128, 1292, 2) f32

    cudaFuncSetAttribute(fft_mel_kernel,
                         cudaFuncAttributeMaxDynamicSharedMemorySize, SMEM_BYTES);
    init_scan<<<129, 256>>>(fb);
    init_perm<<<1, 128>>>(fb);
    fft_mel_kernel<<<dim3(T_FRAMES / 2, 8), 256, SMEM_BYTES>>>(x, out);
}

// round 13
// speedup vs baseline: 9.9931x; 1.0756x over previous
#include <cuda_runtime.h>
#include <cuda_bf16.h>

// ---------------- problem constants ----------------
#define S_LEN    661500
#define HOP      512
#define NFFT     2048
#define T_FRAMES 1292
#define N_BINS   1025
#define N_MELS   128
#define BW       96                // mel band window cap (max real ~54 + ext <32)
#define PWS      1088              // power row stride (34*32)
#define PWBASE   32                // pw starts 32 floats into the buffer (neg-align guard)

// smem skews (index units: float2)
#define SKD(i) ((i) + ((i) >> 4))  // data arrays
#define SKT(i) ((i) + ((i) >> 3))  // twiddle table

#define A2   (SKD(2047) + 2)       // 2176 float2 per data array (4352 floats)
#define TWN  (SKT(511) + 2)        // 576 float2 base twiddle table
#define TW16 256                   // 16x16 stage-1 twiddle table
#define STG_F2 264                 // 528-float output staging (4 planes x 132)
#define SMEM_F2 (2 * A2 + TWN + TW16 + STG_F2)
#define SMEM_BYTES (SMEM_F2 * 8)   // 43584

// ---------------- device statics ----------------
__device__ float  g_bandT[BW * N_MELS];   // [tap][mel], taps relative to align[m]
__device__ int    g_lo[N_MELS];           // align[m] (bank-permuted, may be <0)
__device__ int    g_nch[N_MELS];          // ceil(width'/8), 1..12
__device__ int    g_rawlo[N_MELS], g_rawhi[N_MELS];
__device__ float  g_win[NFFT];
__device__ float2 g_tw2048[512];          // W_2048^k, k<512 (final-stage base)
__device__ float2 g_tw16[TW16];           // [k][p] = W_2048^{8pk}

// ---------------- init pass 1: band extents + window + twiddles ----------------
__global__ void init_scan(const float* __restrict__ fb) {
    const int tid = threadIdx.x;
    if (blockIdx.x == 128) {
        for (int i = tid; i < NFFT; i += 256)
            g_win[i] = 0.5f - 0.5f * cospif((float)i / 1024.0f);
        for (int i = tid; i < 512; i += 256) {
            float s, c; sincospif(-(float)i / 1024.0f, &s, &c);
            g_tw2048[i] = make_float2(c, s);
        }
        if (tid < TW16) {                    // tw16[k*16+p] = W_2048^{8pk}
            int k = tid >> 4, p = tid & 15;
            float s, c; sincospif(-(float)(8 * p * k) / 1024.0f, &s, &c);
            g_tw16[tid] = make_float2(c, s);
        }
        return;
    }
    __shared__ int slo, shi;
    const int m = blockIdx.x;
    if (tid == 0) { slo = N_BINS; shi = -1; }
    __syncthreads();
    int l = N_BINS, h = -1;
    for (int k = tid; k < N_BINS; k += blockDim.x) {
        if (fb[m * N_BINS + k] != 0.0f) { l = min(l, k); h = max(h, k); }
    }
    atomicMin(&slo, l);
    atomicMax(&shi, h);
    __syncthreads();
    if (tid == 0) {
        g_rawlo[m] = (shi >= 0) ? slo : 0;
        g_rawhi[m] = (shi >= 0) ? shi : 0;
    }
}

// ---------------- init pass 2: per-warp optimal bank permutation + band fill ----------------
__global__ void init_perm(const float* __restrict__ fb) {
    const int m    = threadIdx.x;        // 128 threads, warp w owns mels 32w..32w+31
    const int lane = m & 31;
    const int lo = g_rawlo[m];
    const int hi = g_rawhi[m];
    const int width = hi - lo + 1;
    const int key = lo & 31;

    int rank = 0;
#pragma unroll
    for (int l = 0; l < 32; l++) {
        int ok = __shfl_sync(0xffffffffu, key, l);
        rank += (ok < key) || (ok == key && l < lane);
    }
    int best_s = 0, best_max = 1 << 30, best_sum = 1 << 30;
    for (int s = 0; s < 32; s++) {
        int tgt = (rank + s) & 31;
        int ext = (key - tgt) & 31;
        int val = width + ext;
        int vmax = __reduce_max_sync(0xffffffffu, val);
        int vsum = __reduce_add_sync(0xffffffffu, val);
        if (vmax < best_max || (vmax == best_max && vsum < best_sum)) {
            best_max = vmax; best_sum = vsum; best_s = s;
        }
    }
    const int tgt = (rank + best_s) & 31;
    const int align = lo - ((lo - tgt) & 31);   // align ≡ tgt (mod 32), may be < 0
    g_lo[m] = align;
    int wp = hi - align + 1;
    if (wp < 1) wp = 1;
    if (wp > BW) wp = BW;
    g_nch[m] = (wp + 7) >> 3;                   // 1..12 (8-tap granularity)

    for (int i = 0; i < BW; i++) {
        int k = align + i;
        g_bandT[i * N_MELS + m] =
            (k >= lo && k <= hi && k < N_BINS) ? fb[m * N_BINS + k] : 0.0f;
    }
}

// ---------------- complex helpers ----------------
__device__ __forceinline__ float2 cmul(float2 a, float2 b) {
    return make_float2(fmaf(a.x, b.x, -a.y * b.y), fmaf(a.x, b.y, a.y * b.x));
}
__device__ __forceinline__ float2 cadd(float2 a, float2 b) { return make_float2(a.x + b.x, a.y + b.y); }
__device__ __forceinline__ float2 csub(float2 a, float2 b) { return make_float2(a.x - b.x, a.y - b.y); }
__device__ __forceinline__ float2 cmulni(float2 a) { return make_float2(a.y, -a.x); }  // -i*a

// ---------------- radix-8 butterfly (DIT, natural order) ----------------
__device__ __forceinline__ void bfly8(float2* a) {
    const float C = 0.70710678118654752f;
    float2 s02 = cadd(a[0], a[4]), d02 = csub(a[0], a[4]);
    float2 s46 = cadd(a[2], a[6]), d46 = cmulni(csub(a[2], a[6]));
    float2 e0 = cadd(s02, s46), e2 = csub(s02, s46);
    float2 e1 = cadd(d02, d46), e3 = csub(d02, d46);
    float2 s13 = cadd(a[1], a[5]), d13 = csub(a[1], a[5]);
    float2 s57 = cadd(a[3], a[7]), d57 = cmulni(csub(a[3], a[7]));
    float2 o0 = cadd(s13, s57), o2 = csub(s13, s57);
    float2 o1 = cadd(d13, d57), o3 = csub(d13, d57);
    float2 t1 = make_float2(C * (o1.x + o1.y), C * (o1.y - o1.x));
    float2 t2 = cmulni(o2);
    float2 t3 = make_float2(C * (o3.y - o3.x), -C * (o3.x + o3.y));
    a[0] = cadd(e0, o0); a[4] = csub(e0, o0);
    a[1] = cadd(e1, t1); a[5] = csub(e1, t1);
    a[2] = cadd(e2, t2); a[6] = csub(e2, t2);
    a[3] = cadd(e3, t3); a[7] = csub(e3, t3);
}

// ---------------- radix-16 butterfly (4x4 Cooley-Tukey, natural order) ----------------
__device__ __forceinline__ void bfly16(float2* a) {
    const float C8 = 0.70710678118654752f;
    const float C1 = 0.92387953251128676f;   // cos(pi/8)
    const float S1 = 0.38268343236508977f;   // sin(pi/8)
    float2 B[4][4];
#pragma unroll
    for (int n2 = 0; n2 < 4; n2++) {
        float2 x0 = a[n2], x1 = a[n2 + 4], x2 = a[n2 + 8], x3 = a[n2 + 12];
        float2 t0 = cadd(x0, x2), t1 = csub(x0, x2);
        float2 t2 = cadd(x1, x3), t3 = cmulni(csub(x1, x3));
        B[n2][0] = cadd(t0, t2); B[n2][1] = cadd(t1, t3);
        B[n2][2] = csub(t0, t2); B[n2][3] = csub(t1, t3);
    }
    B[1][1] = cmul(B[1][1], make_float2(C1, -S1));
    B[1][2] = cmul(B[1][2], make_float2(C8, -C8));
    B[1][3] = cmul(B[1][3], make_float2(S1, -C1));
    B[2][1] = cmul(B[2][1], make_float2(C8, -C8));
    B[2][2] = cmulni(B[2][2]);
    B[2][3] = cmul(B[2][3], make_float2(-C8, -C8));
    B[3][1] = cmul(B[3][1], make_float2(S1, -C1));
    B[3][2] = cmul(B[3][2], make_float2(-C8, -C8));
    B[3][3] = cmul(B[3][3], make_float2(-C1, S1));
#pragma unroll
    for (int k1 = 0; k1 < 4; k1++) {
        float2 x0 = B[0][k1], x1 = B[1][k1], x2 = B[2][k1], x3 = B[3][k1];
        float2 t0 = cadd(x0, x2), t1 = csub(x0, x2);
        float2 t2 = cadd(x1, x3), t3 = cmulni(csub(x1, x3));
        a[k1]      = cadd(t0, t2);
        a[k1 + 4]  = cadd(t1, t3);
        a[k1 + 8]  = csub(t0, t2);
        a[k1 + 12] = csub(t1, t3);
    }
}

// ---------------- final radix-8 butterfly (L=256): Z[m] = Z[bf + 256m] ----------------
__device__ __forceinline__ void fft8_final(const float2* __restrict__ src,
                                           const float2* __restrict__ tws,
                                           int bf, float2* Z) {
#pragma unroll
    for (int k = 0; k < 8; k++) Z[k] = src[SKD(bf + 256 * k)];
    float2 w1 = tws[SKT(bf)];
    float2 wk = w1;
    Z[1] = cmul(Z[1], wk);
#pragma unroll
    for (int k = 2; k < 8; k++) { wk = cmul(wk, w1); Z[k] = cmul(Z[k], wk); }
    bfly8(Z);
}

// ---------------- fused: 2 frames/block, in-place radix-16/16/8 FFT + power + mel ----------------
__global__ __launch_bounds__(256, 4) void fft_mel_kernel(const float* __restrict__ x,
                                                         float* __restrict__ out) {
    extern __shared__ float2 smem[];
    float2* tws   = smem + 2 * A2;                 // 512-entry skewed (final stage)
    float2* tw16  = smem + 2 * A2 + TWN;           // 16x16 [k][p] (stage 1)
    float*  so    = (float*)(smem + 2 * A2 + TWN + TW16);  // output staging

    const int j  = threadIdx.x;
    const int f  = j >> 7;             // frame within block (0/1)
    const int jj = j & 127;
    const int t  = blockIdx.x * 2 + f;
    const int b  = blockIdx.y;
    const float2* xp = (const float2*)x + (size_t)b * S_LEN;  // (ch0, ch1)

    float2* za = smem + f * A2;        // single in-place array per frame

    for (int i = j; i < 512; i += 256) tws[SKT(i)] = g_tw2048[i];
    if (j < TW16) tw16[j] = g_tw16[j];

    // fused load + radix-16 stage 0 (L=1, unit twiddles): a_k = z[jj+128k] -> za[16jj+m]
    {
        const int base = t * HOP - 1024;
        float2 a[16];
        if (base >= 0 && base <= S_LEN - NFFT) {   // fast path: no reflection (1288/1292)
            const float2* xb = xp + base;
#pragma unroll
            for (int k = 0; k < 16; k++) {
                int n = jj + 128 * k;
                float2 v = __ldg(&xb[n]);
                float  w = g_win[n];
                a[k] = make_float2(w * v.x, w * v.y);
            }
        } else {
#pragma unroll
            for (int k = 0; k < 16; k++) {
                int n = jj + 128 * k;
                int p = base + n;
                p = (p < 0) ? -p : ((p >= S_LEN) ? 2 * S_LEN - 2 - p : p);
                float2 v = __ldg(&xp[p]);
                float  w = g_win[n];
                a[k] = make_float2(w * v.x, w * v.y);
            }
        }
        bfly16(a);
#pragma unroll
        for (int m = 0; m < 16; m++) za[SKD(16 * jj + m)] = a[m];
    }
    __syncthreads();

    // radix-16 stage 1 (L=16), IN-PLACE; twiddles via [k][p] table (conflict-free)
    {
        const int p = jj & 15;
        float2 a[16];
#pragma unroll
        for (int k = 0; k < 16; k++) a[k] = za[SKD(jj + 128 * k)];
#pragma unroll
        for (int k = 1; k < 16; k++) a[k] = cmul(a[k], tw16[k * 16 + p]);
        bfly16(a);
        __syncthreads();                // all reads complete before in-place writes
        const int o = ((jj >> 4) << 8) | p;
#pragma unroll
        for (int m = 0; m < 16; m++) za[SKD(o + 16 * m)] = a[m];
    }
    __syncthreads();

    // fused final radix-8 (L=256) + two-real unpack + power -> pw (aliases za)
    float* pw = (float*)za + PWBASE;    // 32-float negative-align guard precedes pw
    {
        const int bf0 = jj;
        const int bf1 = (jj == 0) ? 128 : 256 - jj;
        float2 ZA[8], ZB[8];
        fft8_final(za, tws, bf0, ZA);   // ZA[m] = Z[bf0 + 256m]
        fft8_final(za, tws, bf1, ZB);   // ZB[m] = Z[bf1 + 256m]
        __syncthreads();                // all reads complete before pw overwrites za

#define PWR(K, ZK, ZN)                                                  \
        {                                                               \
            float sr = (ZK).x + (ZN).x, si = (ZK).y - (ZN).y;           \
            float dr = (ZK).x - (ZN).x, di = (ZK).y + (ZN).y;           \
            pw[(K)]       = 0.25f * (sr * sr + si * si);                \
            pw[PWS + (K)] = 0.25f * (di * di + dr * dr);                \
        }
        if (jj == 0) {
            PWR(0,    ZA[0], ZA[0]);
            PWR(256,  ZA[1], ZA[7]);
            PWR(512,  ZA[2], ZA[6]);
            PWR(768,  ZA[3], ZA[5]);
            PWR(1024, ZA[4], ZA[4]);
#pragma unroll
            for (int m = 0; m < 4; m++) PWR(128 + 256 * m, ZB[m], ZB[7 - m]);
        } else {
#pragma unroll
            for (int m = 0; m < 4; m++) {
                PWR(jj + 256 * m,         ZA[m], ZB[7 - m]);   // Z[k], Z[2048-k]
                PWR((256 - jj) + 256 * m, ZB[m], ZA[7 - m]);
            }
        }
#undef PWR
    }
    // zero guards: leading 32 floats (negative aligns) + tails of both channels
    if (jj < PWBASE) ((float*)za)[jj] = 0.0f;
#pragma unroll
    for (int i = jj; i < (PWS - N_BINS); i += 128) {
        pw[N_BINS + i]       = 0.0f;
        pw[PWS + N_BINS + i] = 0.0f;
    }
    __syncthreads();

    // banded mel: thread j -> mel m = j&127, channel ch = j>>7, BOTH frames
    const int ch = j >> 7;
    const int m  = j & 127;
    const int lo = g_lo[m];             // permuted-aligned window start (may be <0)
    const float* p0 = (const float*)(smem)      + PWBASE + ch * PWS + lo;   // frame 0
    const float* p1 = (const float*)(smem + A2) + PWBASE + ch * PWS + lo;   // frame 1
    const float* bt = g_bandT + m;      // column m, row stride 128 (coalesced)
    const int umax = __reduce_max_sync(0xffffffffu, g_nch[m]);
    float q0 = 0.0f, q1 = 0.0f, q2 = 0.0f, q3 = 0.0f;   // frame 0
    float r0 = 0.0f, r1 = 0.0f, r2 = 0.0f, r3 = 0.0f;   // frame 1

#define MEL_DOT(TAPS)                                                   \
    _Pragma("unroll")                                                   \
    for (int i = 0; i < (TAPS); i += 4) {                               \
        float b0 = bt[(i)     * N_MELS];                                \
        float b1 = bt[(i + 1) * N_MELS];                                \
        float b2 = bt[(i + 2) * N_MELS];                                \
        float b3 = bt[(i + 3) * N_MELS];                                \
        q0 = fmaf(b0, p0[i],     q0);  r0 = fmaf(b0, p1[i],     r0);    \
        q1 = fmaf(b1, p0[i + 1], q1);  r1 = fmaf(b1, p1[i + 1], r1);    \
        q2 = fmaf(b2, p0[i + 2], q2);  r2 = fmaf(b2, p1[i + 2], r2);    \
        q3 = fmaf(b3, p0[i + 3], q3);  r3 = fmaf(b3, p1[i + 3], r3);    \
    }

    switch (umax) {
        case 1:  MEL_DOT(8);  break;
        case 2:  MEL_DOT(16); break;
        case 3:  MEL_DOT(24); break;
        case 4:  MEL_DOT(32); break;
        case 5:  MEL_DOT(40); break;
        case 6:  MEL_DOT(48); break;
        case 7:  MEL_DOT(56); break;
        case 8:  MEL_DOT(64); break;
        case 9:  MEL_DOT(72); break;
        case 10: MEL_DOT(80); break;
        case 11: MEL_DOT(88); break;
        default: MEL_DOT(96); break;
    }
#undef MEL_DOT

    // stage results, then coalesced float4 stores: out float4 = (f0c0,f0c1,f1c0,f1c1)
    so[(0 * 2 + ch) * 132 + m] = (q0 + q1) + (q2 + q3);   // frame 0
    so[(1 * 2 + ch) * 132 + m] = (r0 + r1) + (r2 + r3);   // frame 1
    __syncthreads();
    if (j < 128) {
        float4 v = make_float4(so[j], so[132 + j], so[264 + j], so[396 + j]);
        *(float4*)(out + (((size_t)b * N_MELS + j) * T_FRAMES + blockIdx.x * 2) * 2) = v;
    }
}

// ---------------- entry point ----------------
extern "C" void kernel_launch(void* const* d_in, const int* in_sizes, int n_in,
                              void* d_out, int out_size) {
    const float* x  = (const float*)d_in[0];   // (8, 661500, 2) f32
    const float* fb = (const float*)d_in[1];   // (128, 1025)   f32
    float* out = (float*)d_out;                // (8, 128, 1292, 2) f32

    cudaFuncSetAttribute(fft_mel_kernel,
                         cudaFuncAttributeMaxDynamicSharedMemorySize, SMEM_BYTES);
    init_scan<<<129, 256>>>(fb);
    init_perm<<<1, 128>>>(fb);
    fft_mel_kernel<<<dim3(T_FRAMES / 2, 8), 256, SMEM_BYTES>>>(x, out);
}